// round 5
// baseline (speedup 1.0000x reference)
#include <cuda_runtime.h>
#include <cuda_bf16.h>
#include <cuda_fp16.h>
#include <cstdint>
#include <math.h>

// ---------------- problem constants ----------------
#define BATCH  4
#define NH     8
#define NCH    64
#define SROWS  4096
#define CROWS  8192
#define DMODEL 1024
#define DINNER 512
#define JDIM   129

// ---------------- scratch (device globals; no allocation) ----------------
__device__ float  g_Q [(size_t)BATCH * SROWS * DINNER];
__device__ float  g_KV[(size_t)BATCH * CROWS * 1024];
__device__ __half g_P [(size_t)BATCH * NH * NCH * 64 * JDIM];

// pre-split activations (hi/lo bf16)
__device__ __nv_bfloat16 g_Sh[(size_t)16384 * 1024];
__device__ __nv_bfloat16 g_Sl[(size_t)16384 * 1024];
__device__ __nv_bfloat16 g_Ch[(size_t)32768 * 1024];
__device__ __nv_bfloat16 g_Cl[(size_t)32768 * 1024];
__device__ __nv_bfloat16 g_Oh[(size_t)16384 * 512];
__device__ __nv_bfloat16 g_Ol[(size_t)16384 * 512];

// pre-split weights, bf16 hi/lo, transposed to [N][K]
__device__ __nv_bfloat16 g_Wq_hi [1024 * 512];
__device__ __nv_bfloat16 g_Wq_lo [1024 * 512];
__device__ __nv_bfloat16 g_Wkv_hi[1024 * 1024];
__device__ __nv_bfloat16 g_Wkv_lo[1024 * 1024];
__device__ __nv_bfloat16 g_Wo_hi [512 * 1024];
__device__ __nv_bfloat16 g_Wo_lo [512 * 1024];

// ---------------- asm helpers ----------------
__device__ __forceinline__ uint32_t smem_u32(const void* p) {
    uint32_t a;
    asm("{ .reg .u64 t; cvta.to.shared.u64 t, %1; cvt.u32.u64 %0, t; }" : "=r"(a) : "l"(p));
    return a;
}
#define CP_ASYNC16(dst, src) \
    asm volatile("cp.async.cg.shared.global [%0], [%1], 16;" :: "r"(dst), "l"(src))
#define CP_COMMIT() asm volatile("cp.async.commit_group;" ::: "memory")
#define CP_WAIT(n)  asm volatile("cp.async.wait_group %0;" :: "n"(n) : "memory")

#define LDSM_X4(r, addr) \
    asm volatile("ldmatrix.sync.aligned.m8n8.x4.shared.b16 {%0,%1,%2,%3}, [%4];" \
        : "=r"((r)[0]), "=r"((r)[1]), "=r"((r)[2]), "=r"((r)[3]) : "r"(addr))

__device__ __forceinline__ void mma_bf16(float* c, const uint32_t* a, uint32_t b0, uint32_t b1) {
    asm volatile("mma.sync.aligned.m16n8k16.row.col.f32.bf16.bf16.f32 "
                 "{%0,%1,%2,%3}, {%4,%5,%6,%7}, {%8,%9}, {%0,%1,%2,%3};"
                 : "+f"(c[0]), "+f"(c[1]), "+f"(c[2]), "+f"(c[3])
                 : "r"(a[0]), "r"(a[1]), "r"(a[2]), "r"(a[3]), "r"(b0), "r"(b1));
}

// ---------------- weight split: W[K,N] fp32 -> Whi/Wlo[N,K] bf16 ----------------
__global__ void split_w_kernel(const float* __restrict__ W,
                               __nv_bfloat16* __restrict__ Whi,
                               __nv_bfloat16* __restrict__ Wlo, int K, int N)
{
    __shared__ float t[32][33];
    int kb = blockIdx.x * 32, nb = blockIdx.y * 32;
    int x = threadIdx.x, y = threadIdx.y;
    for (int i = y; i < 32; i += 8)
        t[i][x] = W[(size_t)(kb + i) * N + nb + x];
    __syncthreads();
    for (int i = y; i < 32; i += 8) {
        float w = t[x][i];
        __nv_bfloat16 h = __float2bfloat16(w);
        __nv_bfloat16 l = __float2bfloat16(w - __bfloat162float(h));
        size_t o = (size_t)(nb + i) * K + kb + x;
        Whi[o] = h; Wlo[o] = l;
    }
}

// ---------------- activation split ----------------
__global__ __launch_bounds__(256)
void split_act_kernel(const float* __restrict__ src,
                      __nv_bfloat16* __restrict__ Dh,
                      __nv_bfloat16* __restrict__ Dl, int mode)
{
    size_t idx = (size_t)blockIdx.x * 256 + threadIdx.x;
    int row = (int)(idx >> 8), f4 = (int)(idx & 255);
    const float* p;
    if (mode == 1) { int b = row >> 12, t = row & 4095; p = src + ((size_t)b * 4097 + t + 1) * 1024; }
    else           { int b = row >> 13, r = row & 8191;
                     p = (r < 127) ? nullptr : src + ((size_t)b * 8065 + (r - 127)) * 1024; }
    float4 v = p ? *reinterpret_cast<const float4*>(p + f4 * 4) : make_float4(0.f, 0.f, 0.f, 0.f);
    __nv_bfloat16 hx = __float2bfloat16(v.x), hy = __float2bfloat16(v.y);
    __nv_bfloat16 hz = __float2bfloat16(v.z), hw = __float2bfloat16(v.w);
    __nv_bfloat16 lx = __float2bfloat16(v.x - __bfloat162float(hx));
    __nv_bfloat16 ly = __float2bfloat16(v.y - __bfloat162float(hy));
    __nv_bfloat16 lz = __float2bfloat16(v.z - __bfloat162float(hz));
    __nv_bfloat16 lw = __float2bfloat16(v.w - __bfloat162float(hw));
    size_t o = (size_t)row * 1024 + f4 * 4;
    *reinterpret_cast<__nv_bfloat162*>(Dh + o)     = __halves2bfloat162(hx, hy);
    *reinterpret_cast<__nv_bfloat162*>(Dh + o + 2) = __halves2bfloat162(hz, hw);
    *reinterpret_cast<__nv_bfloat162*>(Dl + o)     = __halves2bfloat162(lx, ly);
    *reinterpret_cast<__nv_bfloat162*>(Dl + o + 2) = __halves2bfloat162(lz, lw);
}

// ---------------- bf16x3 mma.sync GEMM: CTA 128x256, warp tile 64x64, BK=32 ----------------
// smem stage 48KB: A 16KB (128 rows x 128B) + B 32KB (256 rows x 128B); rows pack
// [hi k0..31 | lo k0..31] with 16B-chunk XOR-8 swizzle. 3-stage cp.async pipeline.
// c_mode 0: plain C; 2: scatter rows to d_out (b*4097 + t + 1)
#define GSTG 49152
#define GEMM_SMEM (3 * GSTG)

__global__ __launch_bounds__(256, 1)
void mma_gemm_kernel(const __nv_bfloat16* __restrict__ Ah, const __nv_bfloat16* __restrict__ Al,
                     const __nv_bfloat16* __restrict__ Bh, const __nv_bfloat16* __restrict__ Bl,
                     float* __restrict__ C, int M, int N, int K,
                     float alpha, const float* __restrict__ bias, int c_mode)
{
    extern __shared__ char smem[];
    const uint32_t sbase = smem_u32(smem);
    const int tid = threadIdx.x, warp = tid >> 5, lane = tid & 31;
    const int bn = blockIdx.x, bm = blockIdx.y;
    const int warp_m = warp >> 2, warp_n = warp & 3;   // 2 x 4 warps -> 64x64 tiles
    const int KT = K >> 5;

    // cp.async mapping: 3072 16B chunks per stage, 12 per thread
    const __nv_bfloat16* ld_src[12];
    uint32_t ld_dst[12];
    #pragma unroll
    for (int c = 0; c < 12; c++) {
        int idx = (c << 8) + tid;           // 0..3071
        if (idx < 1024) {                   // A: 128 rows x 8 chunks
            int row = idx >> 3, ch = idx & 7;
            ld_src[c] = ((ch < 4) ? Ah : Al) + (size_t)(bm * 128 + row) * K + (ch & 3) * 8;
            ld_dst[c] = sbase + row * 128 + ((ch ^ (row & 7)) << 4);
        } else {                            // B: 256 rows x 8 chunks
            int id = idx - 1024;
            int row = id >> 3, ch = id & 7;
            ld_src[c] = ((ch < 4) ? Bh : Bl) + (size_t)(bn * 256 + row) * K + (ch & 3) * 8;
            ld_dst[c] = sbase + 16384 + row * 128 + ((ch ^ (row & 7)) << 4);
        }
    }

    auto issue_stage = [&](int kt, int s) {
        #pragma unroll
        for (int c = 0; c < 12; c++)
            CP_ASYNC16(ld_dst[c] + s * GSTG, ld_src[c] + kt * 32);
    };

    float acc[4][8][4] = {};

    const int rlaneA = (lane & 7) + (((lane >> 3) & 1) << 3);
    const int khalfA = (lane >> 4) & 1;
    const int rlaneB = (lane & 7) + (((lane >> 4) & 1) << 3);
    const int khalfB = (lane >> 3) & 1;

    issue_stage(0, 0); CP_COMMIT();
    if (KT > 1) issue_stage(1, 1);
    CP_COMMIT();

    for (int kt = 0; kt < KT; kt++) {
        const int s = kt % 3;
        CP_WAIT(1);
        __syncthreads();
        if (kt + 2 < KT) issue_stage(kt + 2, (kt + 2) % 3);
        CP_COMMIT();

        const uint32_t sA = sbase + s * GSTG;
        const uint32_t sB = sA + 16384;
        #pragma unroll
        for (int kk = 0; kk < 2; kk++) {
            uint32_t aH[4][4], aL[4][4];
            #pragma unroll
            for (int mf = 0; mf < 4; mf++) {
                int r = warp_m * 64 + mf * 16 + rlaneA;
                int ch = kk * 2 + khalfA;
                LDSM_X4(aH[mf], sA + r * 128 + (((ch)     ^ (r & 7)) << 4));
                LDSM_X4(aL[mf], sA + r * 128 + (((ch + 4) ^ (r & 7)) << 4));
            }
            #pragma unroll
            for (int pg = 0; pg < 2; pg++) {
                uint32_t bH[2][4], bL[2][4];
                #pragma unroll
                for (int p = 0; p < 2; p++) {
                    int r = warp_n * 64 + pg * 32 + p * 16 + rlaneB;
                    int ch = kk * 2 + khalfB;
                    LDSM_X4(bH[p], sB + r * 128 + (((ch)     ^ (r & 7)) << 4));
                    LDSM_X4(bL[p], sB + r * 128 + (((ch + 4) ^ (r & 7)) << 4));
                }
                #pragma unroll
                for (int mf = 0; mf < 4; mf++)
                    #pragma unroll
                    for (int nfl = 0; nfl < 4; nfl++) {
                        float* a4 = acc[mf][pg * 4 + nfl];
                        uint32_t b0h = bH[nfl >> 1][(nfl & 1) * 2], b1h = bH[nfl >> 1][(nfl & 1) * 2 + 1];
                        uint32_t b0l = bL[nfl >> 1][(nfl & 1) * 2], b1l = bL[nfl >> 1][(nfl & 1) * 2 + 1];
                        mma_bf16(a4, aH[mf], b0h, b1h);
                        mma_bf16(a4, aH[mf], b0l, b1l);
                        mma_bf16(a4, aL[mf], b0h, b1h);
                    }
            }
        }
        __syncthreads();
    }

    // epilogue
    const int row_in = lane >> 2;
    const int col_in = (lane & 3) * 2;
    #pragma unroll
    for (int mf = 0; mf < 4; mf++) {
        int r0 = bm * 128 + warp_m * 64 + mf * 16 + row_in;
        float *p0, *p1;
        if (c_mode == 2) {
            int b0 = r0 >> 12, t0 = r0 & 4095;
            int r1 = r0 + 8, b1 = r1 >> 12, t1 = r1 & 4095;
            p0 = C + ((size_t)b0 * 4097 + t0 + 1) * N;
            p1 = C + ((size_t)b1 * 4097 + t1 + 1) * N;
        } else {
            p0 = C + (size_t)r0 * N;
            p1 = p0 + (size_t)8 * N;
        }
        #pragma unroll
        for (int nf = 0; nf < 8; nf++) {
            int c0 = bn * 256 + warp_n * 64 + nf * 8 + col_in;
            float bx = 0.f, by = 0.f;
            if (bias) { float2 bv = *reinterpret_cast<const float2*>(bias + c0); bx = bv.x; by = bv.y; }
            float2 v0, v1;
            v0.x = alpha * acc[mf][nf][0] + bx; v0.y = alpha * acc[mf][nf][1] + by;
            v1.x = alpha * acc[mf][nf][2] + bx; v1.y = alpha * acc[mf][nf][3] + by;
            *reinterpret_cast<float2*>(p0 + c0) = v0;
            *reinterpret_cast<float2*>(p1 + c0) = v1;
        }
    }
}

// ---------------- sim + softmax per (b, h, chunk); P stored fp16 ----------------
__global__ __launch_bounds__(256)
void attn_kernel(const float* __restrict__ nullk)
{
    extern __shared__ float sm[];
    float* qs = sm;
    float* ks = sm + 64 * 64;
    const int tid = threadIdx.x;
    const int n = blockIdx.x & 63;
    const int h = (blockIdx.x >> 6) & 7;
    const int b = blockIdx.x >> 9;

    const float* qsrc = g_Q + ((size_t)(b * SROWS + n * 64)) * DINNER + h * 64;
    for (int t = tid; t < 1024; t += 256) {
        int i = t >> 4, d4 = (t & 15) << 2;
        float4 v = *reinterpret_cast<const float4*>(qsrc + (size_t)i * DINNER + d4);
        qs[i * 64 + d4 + 0] = v.x;
        qs[i * 64 + d4 + 1] = v.y;
        qs[i * 64 + d4 + 2] = v.z;
        qs[i * 64 + d4 + 3] = v.w;
    }
    if (tid < 64) ks[tid * 132 + 0] = nullk[h * 64 + tid];
    const float* ksrc = g_KV + (size_t)(b * CROWS + n * 128) * 1024 + h * 64;
    for (int e = tid; e < 128 * 64; e += 256) {
        int j = e >> 6, d = e & 63;
        ks[d * 132 + j + 1] = ksrc[(size_t)j * 1024 + d];
    }
    __syncthreads();

    const int warp = tid >> 5, lane = tid & 31;
    #pragma unroll
    for (int grp = 0; grp < 2; grp++) {
        const int i0 = warp * 8 + grp * 4;
        float acc[4][5] = {};
        #pragma unroll 4
        for (int d = 0; d < 64; d++) {
            float kv[5];
            #pragma unroll
            for (int jj = 0; jj < 5; jj++) {
                int j = lane + jj * 32;
                kv[jj] = (j < JDIM) ? ks[d * 132 + j] : 0.f;
            }
            #pragma unroll
            for (int r = 0; r < 4; r++) {
                float qv = qs[(i0 + r) * 64 + d];
                #pragma unroll
                for (int jj = 0; jj < 5; jj++) acc[r][jj] += qv * kv[jj];
            }
        }
        #pragma unroll
        for (int r = 0; r < 4; r++) {
            float mx = -1e30f;
            #pragma unroll
            for (int jj = 0; jj < 5; jj++)
                if (lane + jj * 32 < JDIM) mx = fmaxf(mx, acc[r][jj]);
            #pragma unroll
            for (int o = 16; o > 0; o >>= 1)
                mx = fmaxf(mx, __shfl_xor_sync(0xffffffffu, mx, o));
            float e5[5], ssum = 0.f;
            #pragma unroll
            for (int jj = 0; jj < 5; jj++) {
                if (lane + jj * 32 < JDIM) { e5[jj] = __expf(acc[r][jj] - mx); ssum += e5[jj]; }
                else e5[jj] = 0.f;
            }
            #pragma unroll
            for (int o = 16; o > 0; o >>= 1)
                ssum += __shfl_xor_sync(0xffffffffu, ssum, o);
            float inv = 1.f / ssum;
            __half* prow = g_P + ((((size_t)(b * NH + h) * NCH + n) * 64) + (i0 + r)) * JDIM;
            #pragma unroll
            for (int jj = 0; jj < 5; jj++) {
                int j = lane + jj * 32;
                if (j < JDIM) prow[j] = __float2half(e5[jj] * inv);
            }
        }
    }
}

// ---------------- fused mix + PV ----------------
// block handles (b, n, ghalf): loads all 8 heads' P (fp16), then for 4 g's:
// phase 1 computes mixed[i][j] = b_th[g] + sum_h W[g,h] P_h[i][j] into smem,
// phase 2 PV with float4 V reads. Output written as hi/lo bf16 for out-proj.
// smem: Ph 8*8256 half (132096) | vs 129*64 f32 (33024) | mixd 64*129 f32 (33024) | w 64 f32 | bt 8 f32
#define PV_SMEM (132096 + 33024 + 33024 + 256 + 32)

__global__ __launch_bounds__(256)
void pvmix_kernel(const float* __restrict__ nullv,
                  const float* __restrict__ Wth, const float* __restrict__ bth)
{
    extern __shared__ char smc[];
    __half* Ph  = reinterpret_cast<__half*>(smc);
    float* vs   = reinterpret_cast<float*>(smc + 132096);
    float* mixd = reinterpret_cast<float*>(smc + 132096 + 33024);
    float* w    = reinterpret_cast<float*>(smc + 132096 + 33024 + 33024);
    float* bt   = w + 64;
    const int tid = threadIdx.x;
    const int gh = blockIdx.x & 1;
    const int n  = (blockIdx.x >> 1) & 63;
    const int b  = blockIdx.x >> 7;

    if (tid < 64) w[tid] = Wth[tid];
    if (tid < 8)  bt[tid] = bth[tid];

    // load all 8 heads' P tile (each 64*129 halves = 1032 uint4)
    #pragma unroll
    for (int h = 0; h < 8; h++) {
        const uint4* src = reinterpret_cast<const uint4*>(
            g_P + (((size_t)(b * NH + h) * NCH + n)) * 64 * JDIM);
        uint4* dst = reinterpret_cast<uint4*>(Ph + h * 8256);
        for (int t = tid; t < 1032; t += 256) dst[t] = src[t];
    }

    const int i = tid >> 2;
    const int dbase = (tid & 3) << 4;

    for (int gl = 0; gl < 4; gl++) {
        const int g = gh * 4 + gl;
        // load V_g (null row j=0, ctx rows 1..128)
        if (tid < 16)
            reinterpret_cast<float4*>(vs)[tid] =
                reinterpret_cast<const float4*>(nullv + g * 64)[tid];
        const float* vsrc = g_KV + (size_t)(b * CROWS + n * 128) * 1024 + 512 + g * 64;
        for (int e = tid; e < 128 * 16; e += 256) {
            int j = e >> 4, d4 = (e & 15) << 2;
            float4 v = *reinterpret_cast<const float4*>(vsrc + (size_t)j * 1024 + d4);
            *reinterpret_cast<float4*>(vs + (j + 1) * 64 + d4) = v;
        }
        __syncthreads();   // also guards Ph on first iter / mixd reuse

        // phase 1: mixed
        float wg[8];
        #pragma unroll
        for (int h = 0; h < 8; h++) wg[h] = w[g * 8 + h];
        const float btg = bt[g];
        for (int e = tid; e < 64 * JDIM; e += 256) {
            float m = btg;
            #pragma unroll
            for (int h = 0; h < 8; h++) m += wg[h] * __half2float(Ph[h * 8256 + e]);
            mixd[e] = m;
        }
        __syncthreads();

        // phase 2: PV
        float4 a0 = {0,0,0,0}, a1 = {0,0,0,0}, a2 = {0,0,0,0}, a3 = {0,0,0,0};
        const float* mrow = mixd + i * JDIM;
        #pragma unroll 4
        for (int j = 0; j < JDIM; j++) {
            float p = mrow[j];
            const float* vr = vs + j * 64 + dbase;
            float4 v0 = *reinterpret_cast<const float4*>(vr);
            float4 v1 = *reinterpret_cast<const float4*>(vr + 4);
            float4 v2 = *reinterpret_cast<const float4*>(vr + 8);
            float4 v3 = *reinterpret_cast<const float4*>(vr + 12);
            a0.x += p * v0.x; a0.y += p * v0.y; a0.z += p * v0.z; a0.w += p * v0.w;
            a1.x += p * v1.x; a1.y += p * v1.y; a1.z += p * v1.z; a1.w += p * v1.w;
            a2.x += p * v2.x; a2.y += p * v2.y; a2.z += p * v2.z; a2.w += p * v2.w;
            a3.x += p * v3.x; a3.y += p * v3.y; a3.z += p * v3.z; a3.w += p * v3.w;
        }
        float accv[16] = {a0.x,a0.y,a0.z,a0.w, a1.x,a1.y,a1.z,a1.w,
                          a2.x,a2.y,a2.z,a2.w, a3.x,a3.y,a3.z,a3.w};
        size_t o = ((size_t)(b * SROWS + n * 64 + i)) * DINNER + g * 64 + dbase;
        #pragma unroll
        for (int dd = 0; dd < 16; dd += 2) {
            __nv_bfloat16 h0 = __float2bfloat16(accv[dd]);
            __nv_bfloat16 h1 = __float2bfloat16(accv[dd + 1]);
            __nv_bfloat16 l0 = __float2bfloat16(accv[dd] - __bfloat162float(h0));
            __nv_bfloat16 l1 = __float2bfloat16(accv[dd + 1] - __bfloat162float(h1));
            *reinterpret_cast<__nv_bfloat162*>(g_Oh + o + dd) = __halves2bfloat162(h0, h1);
            *reinterpret_cast<__nv_bfloat162*>(g_Ol + o + dd) = __halves2bfloat162(l0, l1);
        }
        __syncthreads();
    }
}

// ---------------- zero out t=0 row ----------------
__global__ void zero_row0_kernel(float* __restrict__ out)
{
    int idx = blockIdx.x * blockDim.x + threadIdx.x;
    if (idx < BATCH * DMODEL) {
        int b = idx >> 10, d = idx & 1023;
        out[(size_t)b * 4097 * DMODEL + d] = 0.f;
    }
}

// ---------------- launch ----------------
extern "C" void kernel_launch(void* const* d_in, const int* in_sizes, int n_in,
                              void* d_out, int out_size)
{
    const float* seq   = (const float*)d_in[0];
    const float* ctx   = (const float*)d_in[1];
    const float* Wq    = (const float*)d_in[2];
    const float* Wkv   = (const float*)d_in[3];
    const float* Wout  = (const float*)d_in[4];
    const float* b_out = (const float*)d_in[5];
    const float* nullk = (const float*)d_in[6];
    const float* nullv = (const float*)d_in[7];
    const float* Wth   = (const float*)d_in[8];
    const float* bth   = (const float*)d_in[9];
    float* out = (float*)d_out;

    cudaFuncSetAttribute(mma_gemm_kernel, cudaFuncAttributeMaxDynamicSharedMemorySize, GEMM_SMEM);
    cudaFuncSetAttribute(attn_kernel,  cudaFuncAttributeMaxDynamicSharedMemorySize, 50176);
    cudaFuncSetAttribute(pvmix_kernel, cudaFuncAttributeMaxDynamicSharedMemorySize, PV_SMEM);

    __nv_bfloat16 *wq_hi, *wq_lo, *wkv_hi, *wkv_lo, *wo_hi, *wo_lo;
    __nv_bfloat16 *sh, *sl, *ch_, *cl, *oh, *ol;
    float *q32, *kv32;
    cudaGetSymbolAddress((void**)&wq_hi,  g_Wq_hi);
    cudaGetSymbolAddress((void**)&wq_lo,  g_Wq_lo);
    cudaGetSymbolAddress((void**)&wkv_hi, g_Wkv_hi);
    cudaGetSymbolAddress((void**)&wkv_lo, g_Wkv_lo);
    cudaGetSymbolAddress((void**)&wo_hi,  g_Wo_hi);
    cudaGetSymbolAddress((void**)&wo_lo,  g_Wo_lo);
    cudaGetSymbolAddress((void**)&sh,  g_Sh);
    cudaGetSymbolAddress((void**)&sl,  g_Sl);
    cudaGetSymbolAddress((void**)&ch_, g_Ch);
    cudaGetSymbolAddress((void**)&cl,  g_Cl);
    cudaGetSymbolAddress((void**)&oh,  g_Oh);
    cudaGetSymbolAddress((void**)&ol,  g_Ol);
    cudaGetSymbolAddress((void**)&q32,  g_Q);
    cudaGetSymbolAddress((void**)&kv32, g_KV);

    split_w_kernel<<<dim3(32, 16), dim3(32, 8)>>>(Wq,   wq_hi,  wq_lo,  1024, 512);
    split_w_kernel<<<dim3(32, 32), dim3(32, 8)>>>(Wkv,  wkv_hi, wkv_lo, 1024, 1024);
    split_w_kernel<<<dim3(16, 32), dim3(32, 8)>>>(Wout, wo_hi,  wo_lo,  512, 1024);

    split_act_kernel<<<16384, 256>>>(seq, sh,  sl, 1);
    split_act_kernel<<<32768, 256>>>(ctx, ch_, cl, 2);

    // Q = (seq[:,1:] @ Wq) * 0.125
    mma_gemm_kernel<<<dim3(2, 128), 256, GEMM_SMEM>>>(sh, sl, wq_hi, wq_lo, q32,
                                                      16384, 512, 1024, 0.125f, nullptr, 0);
    // KV = pad(context) @ Wkv
    mma_gemm_kernel<<<dim3(4, 256), 256, GEMM_SMEM>>>(ch_, cl, wkv_hi, wkv_lo, kv32,
                                                      32768, 1024, 1024, 1.0f, nullptr, 0);
    attn_kernel<<<BATCH * NH * NCH, 256, 50176>>>(nullk);
    pvmix_kernel<<<BATCH * NCH * 2, 256, PV_SMEM>>>(nullv, Wth, bth);
    // out = O @ Wout + b_out, scattered to d_out rows t=1..4096
    mma_gemm_kernel<<<dim3(4, 128), 256, GEMM_SMEM>>>(oh, ol, wo_hi, wo_lo, out,
                                                      16384, 1024, 512, 1.0f, b_out, 2);
    zero_row0_kernel<<<4, 1024>>>(out);
}

// round 6
// speedup vs baseline: 1.5717x; 1.5717x over previous
#include <cuda_runtime.h>
#include <cuda_bf16.h>
#include <cstdint>
#include <math.h>

// ---------------- problem constants ----------------
#define BATCH  4
#define NH     8
#define NCH    64
#define SROWS  4096
#define CROWS  8192
#define DMODEL 1024
#define DINNER 512
#define JDIM   129

// ---------------- scratch (device globals; no allocation) ----------------
__device__ float g_Q [(size_t)BATCH * SROWS * DINNER];
__device__ float g_KV[(size_t)BATCH * CROWS * 1024];
__device__ float g_P [(size_t)BATCH * NH * NCH * 64 * JDIM];

// pre-split activations (hi/lo bf16)
__device__ __nv_bfloat16 g_Sh[(size_t)16384 * 1024];
__device__ __nv_bfloat16 g_Sl[(size_t)16384 * 1024];
__device__ __nv_bfloat16 g_Ch[(size_t)32768 * 1024];
__device__ __nv_bfloat16 g_Cl[(size_t)32768 * 1024];
__device__ __nv_bfloat16 g_Oh[(size_t)16384 * 512];
__device__ __nv_bfloat16 g_Ol[(size_t)16384 * 512];

// pre-split weights, bf16 hi/lo, transposed to [N][K]
__device__ __nv_bfloat16 g_Wq_hi [1024 * 512];
__device__ __nv_bfloat16 g_Wq_lo [1024 * 512];
__device__ __nv_bfloat16 g_Wkv_hi[1024 * 1024];
__device__ __nv_bfloat16 g_Wkv_lo[1024 * 1024];
__device__ __nv_bfloat16 g_Wo_hi [512 * 1024];
__device__ __nv_bfloat16 g_Wo_lo [512 * 1024];

// ---------------- asm helpers ----------------
__device__ __forceinline__ uint32_t smem_u32(const void* p) {
    uint32_t a;
    asm("{ .reg .u64 t; cvta.to.shared.u64 t, %1; cvt.u32.u64 %0, t; }" : "=r"(a) : "l"(p));
    return a;
}
#define CP_ASYNC16(dst, src) \
    asm volatile("cp.async.cg.shared.global [%0], [%1], 16;" :: "r"(dst), "l"(src))
#define CP_COMMIT() asm volatile("cp.async.commit_group;" ::: "memory")
#define CP_WAIT(n)  asm volatile("cp.async.wait_group %0;" :: "n"(n) : "memory")

#define LDSM_X4(r, addr) \
    asm volatile("ldmatrix.sync.aligned.m8n8.x4.shared.b16 {%0,%1,%2,%3}, [%4];" \
        : "=r"((r)[0]), "=r"((r)[1]), "=r"((r)[2]), "=r"((r)[3]) : "r"(addr))

__device__ __forceinline__ void mma_bf16(float* c, const uint32_t* a, uint32_t b0, uint32_t b1) {
    asm volatile("mma.sync.aligned.m16n8k16.row.col.f32.bf16.bf16.f32 "
                 "{%0,%1,%2,%3}, {%4,%5,%6,%7}, {%8,%9}, {%0,%1,%2,%3};"
                 : "+f"(c[0]), "+f"(c[1]), "+f"(c[2]), "+f"(c[3])
                 : "r"(a[0]), "r"(a[1]), "r"(a[2]), "r"(a[3]), "r"(b0), "r"(b1));
}

// ---------------- weight split: W[K,N] fp32 -> Whi/Wlo[N,K] bf16 ----------------
__global__ void split_w_kernel(const float* __restrict__ W,
                               __nv_bfloat16* __restrict__ Whi,
                               __nv_bfloat16* __restrict__ Wlo, int K, int N)
{
    __shared__ float t[32][33];
    int kb = blockIdx.x * 32, nb = blockIdx.y * 32;
    int x = threadIdx.x, y = threadIdx.y;
    for (int i = y; i < 32; i += 8)
        t[i][x] = W[(size_t)(kb + i) * N + nb + x];
    __syncthreads();
    for (int i = y; i < 32; i += 8) {
        float w = t[x][i];
        __nv_bfloat16 h = __float2bfloat16(w);
        __nv_bfloat16 l = __float2bfloat16(w - __bfloat162float(h));
        size_t o = (size_t)(nb + i) * K + kb + x;
        Whi[o] = h; Wlo[o] = l;
    }
}

// ---------------- activation split ----------------
__global__ __launch_bounds__(256)
void split_act_kernel(const float* __restrict__ src,
                      __nv_bfloat16* __restrict__ Dh,
                      __nv_bfloat16* __restrict__ Dl, int mode)
{
    size_t idx = (size_t)blockIdx.x * 256 + threadIdx.x;
    int row = (int)(idx >> 8), f4 = (int)(idx & 255);
    const float* p;
    if (mode == 1) { int b = row >> 12, t = row & 4095; p = src + ((size_t)b * 4097 + t + 1) * 1024; }
    else           { int b = row >> 13, r = row & 8191;
                     p = (r < 127) ? nullptr : src + ((size_t)b * 8065 + (r - 127)) * 1024; }
    float4 v = p ? *reinterpret_cast<const float4*>(p + f4 * 4) : make_float4(0.f, 0.f, 0.f, 0.f);
    __nv_bfloat16 hx = __float2bfloat16(v.x), hy = __float2bfloat16(v.y);
    __nv_bfloat16 hz = __float2bfloat16(v.z), hw = __float2bfloat16(v.w);
    __nv_bfloat16 lx = __float2bfloat16(v.x - __bfloat162float(hx));
    __nv_bfloat16 ly = __float2bfloat16(v.y - __bfloat162float(hy));
    __nv_bfloat16 lz = __float2bfloat16(v.z - __bfloat162float(hz));
    __nv_bfloat16 lw = __float2bfloat16(v.w - __bfloat162float(hw));
    size_t o = (size_t)row * 1024 + f4 * 4;
    *reinterpret_cast<__nv_bfloat162*>(Dh + o)     = __halves2bfloat162(hx, hy);
    *reinterpret_cast<__nv_bfloat162*>(Dh + o + 2) = __halves2bfloat162(hz, hw);
    *reinterpret_cast<__nv_bfloat162*>(Dl + o)     = __halves2bfloat162(lx, ly);
    *reinterpret_cast<__nv_bfloat162*>(Dl + o + 2) = __halves2bfloat162(lz, lw);
}

// ---------------- bf16x3 mma.sync GEMM (Round-4 proven config) ----------------
// CTA 128x128, warp tile 64x32, BK=32, 3-stage cp.async pipeline.
#define GSTG 32768
#define GEMM_SMEM (3 * GSTG)

__global__ __launch_bounds__(256, 1)
void mma_gemm_kernel(const __nv_bfloat16* __restrict__ Ah, const __nv_bfloat16* __restrict__ Al,
                     const __nv_bfloat16* __restrict__ Bh, const __nv_bfloat16* __restrict__ Bl,
                     float* __restrict__ C, int M, int N, int K,
                     float alpha, const float* __restrict__ bias, int c_mode)
{
    extern __shared__ char smem[];
    const uint32_t sbase = smem_u32(smem);
    const int tid = threadIdx.x, warp = tid >> 5, lane = tid & 31;
    const int bn = blockIdx.x, bm = blockIdx.y;
    const int warp_m = warp >> 2, warp_n = warp & 3;
    const int KT = K >> 5;

    const __nv_bfloat16* ld_src[8];
    uint32_t ld_dst[8];
    #pragma unroll
    for (int c = 0; c < 8; c++) {
        int idx = (c << 8) + tid;
        int isB = idx >> 10;
        int id = idx & 1023;
        int row = id >> 3, ch = id & 7;
        const __nv_bfloat16* base;
        if (!isB) base = ((ch < 4) ? Ah : Al) + (size_t)(bm * 128 + row) * K + (ch & 3) * 8;
        else      base = ((ch < 4) ? Bh : Bl) + (size_t)(bn * 128 + row) * K + (ch & 3) * 8;
        ld_src[c] = base;
        ld_dst[c] = sbase + (isB ? 16384 : 0) + row * 128 + ((ch ^ (row & 7)) << 4);
    }

    auto issue_stage = [&](int kt, int s) {
        #pragma unroll
        for (int c = 0; c < 8; c++)
            CP_ASYNC16(ld_dst[c] + s * GSTG, ld_src[c] + kt * 32);
    };

    float acc[4][4][4] = {};

    const int rlaneA = (lane & 7) + (((lane >> 3) & 1) << 3);
    const int khalfA = (lane >> 4) & 1;
    const int rlaneB = (lane & 7) + (((lane >> 4) & 1) << 3);
    const int khalfB = (lane >> 3) & 1;

    issue_stage(0, 0); CP_COMMIT();
    if (KT > 1) issue_stage(1, 1);
    CP_COMMIT();

    for (int kt = 0; kt < KT; kt++) {
        const int s = kt % 3;
        CP_WAIT(1);
        __syncthreads();
        if (kt + 2 < KT) issue_stage(kt + 2, (kt + 2) % 3);
        CP_COMMIT();

        const uint32_t sA = sbase + s * GSTG;
        const uint32_t sB = sA + 16384;
        #pragma unroll
        for (int kk = 0; kk < 2; kk++) {
            uint32_t aH[4][4], aL[4][4], bH[2][4], bL[2][4];
            #pragma unroll
            for (int mf = 0; mf < 4; mf++) {
                int r = warp_m * 64 + mf * 16 + rlaneA;
                int ch = kk * 2 + khalfA;
                LDSM_X4(aH[mf], sA + r * 128 + (((ch)     ^ (r & 7)) << 4));
                LDSM_X4(aL[mf], sA + r * 128 + (((ch + 4) ^ (r & 7)) << 4));
            }
            #pragma unroll
            for (int p = 0; p < 2; p++) {
                int r = warp_n * 32 + p * 16 + rlaneB;
                int ch = kk * 2 + khalfB;
                LDSM_X4(bH[p], sB + r * 128 + (((ch)     ^ (r & 7)) << 4));
                LDSM_X4(bL[p], sB + r * 128 + (((ch + 4) ^ (r & 7)) << 4));
            }
            #pragma unroll
            for (int mf = 0; mf < 4; mf++)
                #pragma unroll
                for (int nf = 0; nf < 4; nf++) {
                    uint32_t b0h = bH[nf >> 1][(nf & 1) * 2], b1h = bH[nf >> 1][(nf & 1) * 2 + 1];
                    uint32_t b0l = bL[nf >> 1][(nf & 1) * 2], b1l = bL[nf >> 1][(nf & 1) * 2 + 1];
                    mma_bf16(acc[mf][nf], aH[mf], b0h, b1h);
                    mma_bf16(acc[mf][nf], aH[mf], b0l, b1l);
                    mma_bf16(acc[mf][nf], aL[mf], b0h, b1h);
                }
        }
        __syncthreads();
    }

    const int row_in = lane >> 2;
    const int col_in = (lane & 3) * 2;
    #pragma unroll
    for (int mf = 0; mf < 4; mf++) {
        int r0 = bm * 128 + warp_m * 64 + mf * 16 + row_in;
        float *p0, *p1;
        if (c_mode == 2) {
            int b0 = r0 >> 12, t0 = r0 & 4095;
            int r1 = r0 + 8, b1 = r1 >> 12, t1 = r1 & 4095;
            p0 = C + ((size_t)b0 * 4097 + t0 + 1) * N;
            p1 = C + ((size_t)b1 * 4097 + t1 + 1) * N;
        } else {
            p0 = C + (size_t)r0 * N;
            p1 = p0 + (size_t)8 * N;
        }
        #pragma unroll
        for (int nf = 0; nf < 4; nf++) {
            int c0 = bn * 128 + warp_n * 32 + nf * 8 + col_in;
            float bx = 0.f, by = 0.f;
            if (bias) { float2 bv = *reinterpret_cast<const float2*>(bias + c0); bx = bv.x; by = bv.y; }
            float2 v0, v1;
            v0.x = alpha * acc[mf][nf][0] + bx; v0.y = alpha * acc[mf][nf][1] + by;
            v1.x = alpha * acc[mf][nf][2] + bx; v1.y = alpha * acc[mf][nf][3] + by;
            *reinterpret_cast<float2*>(p0 + c0) = v0;
            *reinterpret_cast<float2*>(p1 + c0) = v1;
        }
    }
}

// ---------------- sim + softmax per (b, h, chunk); P fp32 ----------------
__global__ __launch_bounds__(256)
void attn_kernel(const float* __restrict__ nullk)
{
    extern __shared__ float sm[];
    float* qs = sm;
    float* ks = sm + 64 * 64;
    const int tid = threadIdx.x;
    const int n = blockIdx.x & 63;
    const int h = (blockIdx.x >> 6) & 7;
    const int b = blockIdx.x >> 9;

    const float* qsrc = g_Q + ((size_t)(b * SROWS + n * 64)) * DINNER + h * 64;
    for (int t = tid; t < 1024; t += 256) {
        int i = t >> 4, d4 = (t & 15) << 2;
        float4 v = *reinterpret_cast<const float4*>(qsrc + (size_t)i * DINNER + d4);
        qs[i * 64 + d4 + 0] = v.x;
        qs[i * 64 + d4 + 1] = v.y;
        qs[i * 64 + d4 + 2] = v.z;
        qs[i * 64 + d4 + 3] = v.w;
    }
    if (tid < 64) ks[tid * 132 + 0] = nullk[h * 64 + tid];
    const float* ksrc = g_KV + (size_t)(b * CROWS + n * 128) * 1024 + h * 64;
    for (int e = tid; e < 128 * 64; e += 256) {
        int j = e >> 6, d = e & 63;
        ks[d * 132 + j + 1] = ksrc[(size_t)j * 1024 + d];
    }
    __syncthreads();

    const int warp = tid >> 5, lane = tid & 31;
    #pragma unroll
    for (int grp = 0; grp < 2; grp++) {
        const int i0 = warp * 8 + grp * 4;
        float acc[4][5] = {};
        #pragma unroll 4
        for (int d = 0; d < 64; d++) {
            float kv[5];
            #pragma unroll
            for (int jj = 0; jj < 5; jj++) {
                int j = lane + jj * 32;
                kv[jj] = (j < JDIM) ? ks[d * 132 + j] : 0.f;
            }
            #pragma unroll
            for (int r = 0; r < 4; r++) {
                float qv = qs[(i0 + r) * 64 + d];
                #pragma unroll
                for (int jj = 0; jj < 5; jj++) acc[r][jj] += qv * kv[jj];
            }
        }
        #pragma unroll
        for (int r = 0; r < 4; r++) {
            float mx = -1e30f;
            #pragma unroll
            for (int jj = 0; jj < 5; jj++)
                if (lane + jj * 32 < JDIM) mx = fmaxf(mx, acc[r][jj]);
            #pragma unroll
            for (int o = 16; o > 0; o >>= 1)
                mx = fmaxf(mx, __shfl_xor_sync(0xffffffffu, mx, o));
            float e5[5], ssum = 0.f;
            #pragma unroll
            for (int jj = 0; jj < 5; jj++) {
                if (lane + jj * 32 < JDIM) { e5[jj] = __expf(acc[r][jj] - mx); ssum += e5[jj]; }
                else e5[jj] = 0.f;
            }
            #pragma unroll
            for (int o = 16; o > 0; o >>= 1)
                ssum += __shfl_xor_sync(0xffffffffu, ssum, o);
            float inv = 1.f / ssum;
            float* prow = g_P + ((((size_t)(b * NH + h) * NCH + n) * 64) + (i0 + r)) * JDIM;
            #pragma unroll
            for (int jj = 0; jj < 5; jj++) {
                int j = lane + jj * 32;
                if (j < JDIM) prow[j] = e5[jj] * inv;
            }
        }
    }
}

// ---------------- PV with inline head-mix ----------------
// block per (b, g, n): mixed[i][j] = b_th[g] + sum_h W[g,h] P_h[i][j]
// (P tiles read from global; 54MB total is L2-resident across the 8x reuse),
// then out[i,d] = sum_j mixed[i][j] V_g[j][d]; write hi/lo bf16 for out-proj.
// smem: mixed 64*129 f32 | vs 129*64 f32 = 66048 bytes
__global__ __launch_bounds__(256)
void pvmix_kernel(const float* __restrict__ nullv,
                  const float* __restrict__ Wth, const float* __restrict__ bth)
{
    extern __shared__ float sm[];
    float* mixd = sm;               // [i][j]
    float* vs   = sm + 64 * JDIM;   // [j][d]
    const int tid = threadIdx.x;
    const int n = blockIdx.x & 63;
    const int g = (blockIdx.x >> 6) & 7;
    const int b = blockIdx.x >> 9;

    // V_g tile (null row at j=0)
    if (tid < 16)
        reinterpret_cast<float4*>(vs)[tid] =
            reinterpret_cast<const float4*>(nullv + g * 64)[tid];
    const float* vsrc = g_KV + (size_t)(b * CROWS + n * 128) * 1024 + 512 + g * 64;
    for (int e = tid; e < 128 * 16; e += 256) {
        int j = e >> 4, d4 = (e & 15) << 2;
        float4 v = *reinterpret_cast<const float4*>(vsrc + (size_t)j * 1024 + d4);
        *reinterpret_cast<float4*>(vs + (j + 1) * 64 + d4) = v;
    }

    // inline mix: read 8 heads' P tiles from global
    float wg[8];
    #pragma unroll
    for (int h = 0; h < 8; h++) wg[h] = __ldg(Wth + g * 8 + h);
    const float btg = __ldg(bth + g);
    const size_t hstride = (size_t)NCH * 64 * JDIM;
    const float* pbase = g_P + ((size_t)(b * NH) * NCH + n) * 64 * JDIM;
    for (int e = tid; e < 64 * JDIM; e += 256) {
        float m = btg;
        #pragma unroll
        for (int h = 0; h < 8; h++) m += wg[h] * __ldg(pbase + h * hstride + e);
        mixd[e] = m;
    }
    __syncthreads();

    // PV
    const int i = tid >> 2;
    const int dbase = (tid & 3) << 4;
    float acc[16] = {};
    const float* mrow = mixd + i * JDIM;
    for (int j = 0; j < JDIM; j++) {
        float p = mrow[j];
        #pragma unroll
        for (int dd = 0; dd < 16; dd++)
            acc[dd] += p * vs[j * 64 + dbase + dd];
    }
    size_t o = ((size_t)(b * SROWS + n * 64 + i)) * DINNER + g * 64 + dbase;
    #pragma unroll
    for (int dd = 0; dd < 16; dd += 2) {
        __nv_bfloat16 h0 = __float2bfloat16(acc[dd]);
        __nv_bfloat16 h1 = __float2bfloat16(acc[dd + 1]);
        __nv_bfloat16 l0 = __float2bfloat16(acc[dd] - __bfloat162float(h0));
        __nv_bfloat16 l1 = __float2bfloat16(acc[dd + 1] - __bfloat162float(h1));
        *reinterpret_cast<__nv_bfloat162*>(g_Oh + o + dd) = __halves2bfloat162(h0, h1);
        *reinterpret_cast<__nv_bfloat162*>(g_Ol + o + dd) = __halves2bfloat162(l0, l1);
    }
}

// ---------------- zero out t=0 row ----------------
__global__ void zero_row0_kernel(float* __restrict__ out)
{
    int idx = blockIdx.x * blockDim.x + threadIdx.x;
    if (idx < BATCH * DMODEL) {
        int b = idx >> 10, d = idx & 1023;
        out[(size_t)b * 4097 * DMODEL + d] = 0.f;
    }
}

// ---------------- launch ----------------
extern "C" void kernel_launch(void* const* d_in, const int* in_sizes, int n_in,
                              void* d_out, int out_size)
{
    const float* seq   = (const float*)d_in[0];
    const float* ctx   = (const float*)d_in[1];
    const float* Wq    = (const float*)d_in[2];
    const float* Wkv   = (const float*)d_in[3];
    const float* Wout  = (const float*)d_in[4];
    const float* b_out = (const float*)d_in[5];
    const float* nullk = (const float*)d_in[6];
    const float* nullv = (const float*)d_in[7];
    const float* Wth   = (const float*)d_in[8];
    const float* bth   = (const float*)d_in[9];
    float* out = (float*)d_out;

    cudaFuncSetAttribute(mma_gemm_kernel, cudaFuncAttributeMaxDynamicSharedMemorySize, GEMM_SMEM);
    cudaFuncSetAttribute(attn_kernel,  cudaFuncAttributeMaxDynamicSharedMemorySize, 50176);
    cudaFuncSetAttribute(pvmix_kernel, cudaFuncAttributeMaxDynamicSharedMemorySize, 66048);

    __nv_bfloat16 *wq_hi, *wq_lo, *wkv_hi, *wkv_lo, *wo_hi, *wo_lo;
    __nv_bfloat16 *sh, *sl, *ch_, *cl, *oh, *ol;
    float *q32, *kv32;
    cudaGetSymbolAddress((void**)&wq_hi,  g_Wq_hi);
    cudaGetSymbolAddress((void**)&wq_lo,  g_Wq_lo);
    cudaGetSymbolAddress((void**)&wkv_hi, g_Wkv_hi);
    cudaGetSymbolAddress((void**)&wkv_lo, g_Wkv_lo);
    cudaGetSymbolAddress((void**)&wo_hi,  g_Wo_hi);
    cudaGetSymbolAddress((void**)&wo_lo,  g_Wo_lo);
    cudaGetSymbolAddress((void**)&sh,  g_Sh);
    cudaGetSymbolAddress((void**)&sl,  g_Sl);
    cudaGetSymbolAddress((void**)&ch_, g_Ch);
    cudaGetSymbolAddress((void**)&cl,  g_Cl);
    cudaGetSymbolAddress((void**)&oh,  g_Oh);
    cudaGetSymbolAddress((void**)&ol,  g_Ol);
    cudaGetSymbolAddress((void**)&q32,  g_Q);
    cudaGetSymbolAddress((void**)&kv32, g_KV);

    // order chosen so the KV GEMM sits in ncu's captured slot (4th launch)
    split_w_kernel<<<dim3(32, 32), dim3(32, 8)>>>(Wkv,  wkv_hi, wkv_lo, 1024, 1024);  // 1
    split_act_kernel<<<32768, 256>>>(ctx, ch_, cl, 2);                                // 2
    split_act_kernel<<<16384, 256>>>(seq, sh,  sl, 1);                                // 3
    // KV = pad(context) @ Wkv                                                        // 4 (profiled)
    mma_gemm_kernel<<<dim3(8, 256), 256, GEMM_SMEM>>>(ch_, cl, wkv_hi, wkv_lo, kv32,
                                                      32768, 1024, 1024, 1.0f, nullptr, 0);
    split_w_kernel<<<dim3(32, 16), dim3(32, 8)>>>(Wq,   wq_hi,  wq_lo,  1024, 512);   // 5
    // Q = (seq[:,1:] @ Wq) * 0.125                                                   // 6
    mma_gemm_kernel<<<dim3(4, 128), 256, GEMM_SMEM>>>(sh, sl, wq_hi, wq_lo, q32,
                                                      16384, 512, 1024, 0.125f, nullptr, 0);
    attn_kernel<<<BATCH * NH * NCH, 256, 50176>>>(nullk);                             // 7
    pvmix_kernel<<<BATCH * NH * NCH, 256, 66048>>>(nullv, Wth, bth);                  // 8
    split_w_kernel<<<dim3(16, 32), dim3(32, 8)>>>(Wout, wo_hi,  wo_lo,  512, 1024);   // 9
    // out = O @ Wout + b_out, scattered to d_out rows t=1..4096                      // 10
    mma_gemm_kernel<<<dim3(8, 128), 256, GEMM_SMEM>>>(oh, ol, wo_hi, wo_lo, out,
                                                      16384, 1024, 512, 1.0f, b_out, 2);
    zero_row0_kernel<<<4, 1024>>>(out);                                               // 11
}

// round 7
// speedup vs baseline: 1.6969x; 1.0796x over previous
#include <cuda_runtime.h>
#include <cuda_bf16.h>
#include <cstdint>
#include <math.h>

// ---------------- problem constants ----------------
#define BATCH  4
#define NH     8
#define NCH    64
#define SROWS  4096
#define CROWS  8192
#define DMODEL 1024
#define DINNER 512
#define JDIM   129

// ---------------- scratch (device globals; no allocation) ----------------
__device__ float g_Q [(size_t)BATCH * SROWS * DINNER];
__device__ float g_KV[(size_t)BATCH * CROWS * 1024];
__device__ float g_P [(size_t)BATCH * NH * NCH * 64 * JDIM];

// pre-split activations (hi/lo bf16)
__device__ __nv_bfloat16 g_Sh[(size_t)16384 * 1024];
__device__ __nv_bfloat16 g_Sl[(size_t)16384 * 1024];
__device__ __nv_bfloat16 g_Ch[(size_t)32768 * 1024];
__device__ __nv_bfloat16 g_Cl[(size_t)32768 * 1024];
__device__ __nv_bfloat16 g_Oh[(size_t)16384 * 512];
__device__ __nv_bfloat16 g_Ol[(size_t)16384 * 512];

// pre-split weights, bf16 hi/lo, transposed to [N][K]
__device__ __nv_bfloat16 g_Wq_hi [1024 * 512];
__device__ __nv_bfloat16 g_Wq_lo [1024 * 512];
__device__ __nv_bfloat16 g_Wkv_hi[1024 * 1024];
__device__ __nv_bfloat16 g_Wkv_lo[1024 * 1024];
__device__ __nv_bfloat16 g_Wo_hi [512 * 1024];
__device__ __nv_bfloat16 g_Wo_lo [512 * 1024];

// ---------------- asm helpers ----------------
__device__ __forceinline__ uint32_t smem_u32(const void* p) {
    uint32_t a;
    asm("{ .reg .u64 t; cvta.to.shared.u64 t, %1; cvt.u32.u64 %0, t; }" : "=r"(a) : "l"(p));
    return a;
}
#define CP_ASYNC16(dst, src) \
    asm volatile("cp.async.cg.shared.global [%0], [%1], 16;" :: "r"(dst), "l"(src))
#define CP_COMMIT() asm volatile("cp.async.commit_group;" ::: "memory")
#define CP_WAIT(n)  asm volatile("cp.async.wait_group %0;" :: "n"(n) : "memory")

#define LDSM_X4(r, addr) \
    asm volatile("ldmatrix.sync.aligned.m8n8.x4.shared.b16 {%0,%1,%2,%3}, [%4];" \
        : "=r"((r)[0]), "=r"((r)[1]), "=r"((r)[2]), "=r"((r)[3]) : "r"(addr))

__device__ __forceinline__ void mma_bf16(float* c, const uint32_t* a, uint32_t b0, uint32_t b1) {
    asm volatile("mma.sync.aligned.m16n8k16.row.col.f32.bf16.bf16.f32 "
                 "{%0,%1,%2,%3}, {%4,%5,%6,%7}, {%8,%9}, {%0,%1,%2,%3};"
                 : "+f"(c[0]), "+f"(c[1]), "+f"(c[2]), "+f"(c[3])
                 : "r"(a[0]), "r"(a[1]), "r"(a[2]), "r"(a[3]), "r"(b0), "r"(b1));
}

// ---------------- weight split: W[K,N] fp32 -> Whi/Wlo[N,K] bf16 ----------------
__global__ void split_w_kernel(const float* __restrict__ W,
                               __nv_bfloat16* __restrict__ Whi,
                               __nv_bfloat16* __restrict__ Wlo, int K, int N)
{
    __shared__ float t[32][33];
    int kb = blockIdx.x * 32, nb = blockIdx.y * 32;
    int x = threadIdx.x, y = threadIdx.y;
    for (int i = y; i < 32; i += 8)
        t[i][x] = W[(size_t)(kb + i) * N + nb + x];
    __syncthreads();
    for (int i = y; i < 32; i += 8) {
        float w = t[x][i];
        __nv_bfloat16 h = __float2bfloat16(w);
        __nv_bfloat16 l = __float2bfloat16(w - __bfloat162float(h));
        size_t o = (size_t)(nb + i) * K + kb + x;
        Whi[o] = h; Wlo[o] = l;
    }
}

// ---------------- activation split ----------------
__global__ __launch_bounds__(256)
void split_act_kernel(const float* __restrict__ src,
                      __nv_bfloat16* __restrict__ Dh,
                      __nv_bfloat16* __restrict__ Dl, int mode)
{
    size_t idx = (size_t)blockIdx.x * 256 + threadIdx.x;
    int row = (int)(idx >> 8), f4 = (int)(idx & 255);
    const float* p;
    if (mode == 1) { int b = row >> 12, t = row & 4095; p = src + ((size_t)b * 4097 + t + 1) * 1024; }
    else           { int b = row >> 13, r = row & 8191;
                     p = (r < 127) ? nullptr : src + ((size_t)b * 8065 + (r - 127)) * 1024; }
    float4 v = p ? *reinterpret_cast<const float4*>(p + f4 * 4) : make_float4(0.f, 0.f, 0.f, 0.f);
    __nv_bfloat16 hx = __float2bfloat16(v.x), hy = __float2bfloat16(v.y);
    __nv_bfloat16 hz = __float2bfloat16(v.z), hw = __float2bfloat16(v.w);
    __nv_bfloat16 lx = __float2bfloat16(v.x - __bfloat162float(hx));
    __nv_bfloat16 ly = __float2bfloat16(v.y - __bfloat162float(hy));
    __nv_bfloat16 lz = __float2bfloat16(v.z - __bfloat162float(hz));
    __nv_bfloat16 lw = __float2bfloat16(v.w - __bfloat162float(hw));
    size_t o = (size_t)row * 1024 + f4 * 4;
    *reinterpret_cast<__nv_bfloat162*>(Dh + o)     = __halves2bfloat162(hx, hy);
    *reinterpret_cast<__nv_bfloat162*>(Dh + o + 2) = __halves2bfloat162(hz, hw);
    *reinterpret_cast<__nv_bfloat162*>(Dl + o)     = __halves2bfloat162(lx, ly);
    *reinterpret_cast<__nv_bfloat162*>(Dl + o + 2) = __halves2bfloat162(lz, lw);
}

// ---------------- bf16x3 mma.sync GEMM: CTA 128x128, warp 64x32, BK=32, 2 CTAs/SM ----------------
#define GSTG 32768
#define GEMM_SMEM (3 * GSTG)

__global__ __launch_bounds__(256, 2)
void mma_gemm_kernel(const __nv_bfloat16* __restrict__ Ah, const __nv_bfloat16* __restrict__ Al,
                     const __nv_bfloat16* __restrict__ Bh, const __nv_bfloat16* __restrict__ Bl,
                     float* __restrict__ C, int M, int N, int K,
                     float alpha, const float* __restrict__ bias, int c_mode)
{
    extern __shared__ char smem[];
    const uint32_t sbase = smem_u32(smem);
    const int tid = threadIdx.x, warp = tid >> 5, lane = tid & 31;
    const int bn = blockIdx.x, bm = blockIdx.y;
    const int warp_m = warp >> 2, warp_n = warp & 3;
    const int KT = K >> 5;

    const __nv_bfloat16* ld_src[8];
    uint32_t ld_dst[8];
    #pragma unroll
    for (int c = 0; c < 8; c++) {
        int idx = (c << 8) + tid;
        int isB = idx >> 10;
        int id = idx & 1023;
        int row = id >> 3, ch = id & 7;
        const __nv_bfloat16* base;
        if (!isB) base = ((ch < 4) ? Ah : Al) + (size_t)(bm * 128 + row) * K + (ch & 3) * 8;
        else      base = ((ch < 4) ? Bh : Bl) + (size_t)(bn * 128 + row) * K + (ch & 3) * 8;
        ld_src[c] = base;
        ld_dst[c] = sbase + (isB ? 16384 : 0) + row * 128 + ((ch ^ (row & 7)) << 4);
    }

    auto issue_stage = [&](int kt, int s) {
        #pragma unroll
        for (int c = 0; c < 8; c++)
            CP_ASYNC16(ld_dst[c] + s * GSTG, ld_src[c] + kt * 32);
    };

    float acc[4][4][4] = {};

    const int rlaneA = (lane & 7) + (((lane >> 3) & 1) << 3);
    const int khalfA = (lane >> 4) & 1;
    const int rlaneB = (lane & 7) + (((lane >> 4) & 1) << 3);
    const int khalfB = (lane >> 3) & 1;

    issue_stage(0, 0); CP_COMMIT();
    if (KT > 1) issue_stage(1, 1);
    CP_COMMIT();

    for (int kt = 0; kt < KT; kt++) {
        const int s = kt % 3;
        CP_WAIT(1);
        __syncthreads();
        if (kt + 2 < KT) issue_stage(kt + 2, (kt + 2) % 3);
        CP_COMMIT();

        const uint32_t sA = sbase + s * GSTG;
        const uint32_t sB = sA + 16384;
        #pragma unroll
        for (int kk = 0; kk < 2; kk++) {
            uint32_t aH[4][4], aL[4][4];
            #pragma unroll
            for (int mf = 0; mf < 4; mf++) {
                int r = warp_m * 64 + mf * 16 + rlaneA;
                int ch = kk * 2 + khalfA;
                LDSM_X4(aH[mf], sA + r * 128 + (((ch)     ^ (r & 7)) << 4));
                LDSM_X4(aL[mf], sA + r * 128 + (((ch + 4) ^ (r & 7)) << 4));
            }
            // consume B fragments immediately per 16-row group to cap live regs
            #pragma unroll
            for (int p = 0; p < 2; p++) {
                uint32_t bH[4], bL[4];
                int r = warp_n * 32 + p * 16 + rlaneB;
                int ch = kk * 2 + khalfB;
                LDSM_X4(bH, sB + r * 128 + (((ch)     ^ (r & 7)) << 4));
                LDSM_X4(bL, sB + r * 128 + (((ch + 4) ^ (r & 7)) << 4));
                #pragma unroll
                for (int q = 0; q < 2; q++) {
                    const int nf = p * 2 + q;
                    uint32_t b0h = bH[q * 2], b1h = bH[q * 2 + 1];
                    uint32_t b0l = bL[q * 2], b1l = bL[q * 2 + 1];
                    #pragma unroll
                    for (int mf = 0; mf < 4; mf++) {
                        mma_bf16(acc[mf][nf], aH[mf], b0h, b1h);
                        mma_bf16(acc[mf][nf], aH[mf], b0l, b1l);
                        mma_bf16(acc[mf][nf], aL[mf], b0h, b1h);
                    }
                }
            }
        }
        __syncthreads();
    }

    const int row_in = lane >> 2;
    const int col_in = (lane & 3) * 2;
    #pragma unroll
    for (int mf = 0; mf < 4; mf++) {
        int r0 = bm * 128 + warp_m * 64 + mf * 16 + row_in;
        float *p0, *p1;
        if (c_mode == 2) {
            int b0 = r0 >> 12, t0 = r0 & 4095;
            int r1 = r0 + 8, b1 = r1 >> 12, t1 = r1 & 4095;
            p0 = C + ((size_t)b0 * 4097 + t0 + 1) * N;
            p1 = C + ((size_t)b1 * 4097 + t1 + 1) * N;
        } else {
            p0 = C + (size_t)r0 * N;
            p1 = p0 + (size_t)8 * N;
        }
        #pragma unroll
        for (int nf = 0; nf < 4; nf++) {
            int c0 = bn * 128 + warp_n * 32 + nf * 8 + col_in;
            float bx = 0.f, by = 0.f;
            if (bias) { float2 bv = *reinterpret_cast<const float2*>(bias + c0); bx = bv.x; by = bv.y; }
            float2 v0, v1;
            v0.x = alpha * acc[mf][nf][0] + bx; v0.y = alpha * acc[mf][nf][1] + by;
            v1.x = alpha * acc[mf][nf][2] + bx; v1.y = alpha * acc[mf][nf][3] + by;
            *reinterpret_cast<float2*>(p0 + c0) = v0;
            *reinterpret_cast<float2*>(p1 + c0) = v1;
        }
    }
}

// ---------------- sim + softmax per (b, h, chunk); P fp32 ----------------
__global__ __launch_bounds__(256)
void attn_kernel(const float* __restrict__ nullk)
{
    extern __shared__ float sm[];
    float* qs = sm;
    float* ks = sm + 64 * 64;
    const int tid = threadIdx.x;
    const int n = blockIdx.x & 63;
    const int h = (blockIdx.x >> 6) & 7;
    const int b = blockIdx.x >> 9;

    const float* qsrc = g_Q + ((size_t)(b * SROWS + n * 64)) * DINNER + h * 64;
    for (int t = tid; t < 1024; t += 256) {
        int i = t >> 4, d4 = (t & 15) << 2;
        float4 v = *reinterpret_cast<const float4*>(qsrc + (size_t)i * DINNER + d4);
        qs[i * 64 + d4 + 0] = v.x;
        qs[i * 64 + d4 + 1] = v.y;
        qs[i * 64 + d4 + 2] = v.z;
        qs[i * 64 + d4 + 3] = v.w;
    }
    if (tid < 64) ks[tid * 132 + 0] = nullk[h * 64 + tid];
    const float* ksrc = g_KV + (size_t)(b * CROWS + n * 128) * 1024 + h * 64;
    for (int e = tid; e < 128 * 64; e += 256) {
        int j = e >> 6, d = e & 63;
        ks[d * 132 + j + 1] = ksrc[(size_t)j * 1024 + d];
    }
    __syncthreads();

    const int warp = tid >> 5, lane = tid & 31;
    #pragma unroll
    for (int grp = 0; grp < 2; grp++) {
        const int i0 = warp * 8 + grp * 4;
        float acc[4][5] = {};
        #pragma unroll 4
        for (int d = 0; d < 64; d++) {
            float kv[5];
            #pragma unroll
            for (int jj = 0; jj < 5; jj++) {
                int j = lane + jj * 32;
                kv[jj] = (j < JDIM) ? ks[d * 132 + j] : 0.f;
            }
            #pragma unroll
            for (int r = 0; r < 4; r++) {
                float qv = qs[(i0 + r) * 64 + d];
                #pragma unroll
                for (int jj = 0; jj < 5; jj++) acc[r][jj] += qv * kv[jj];
            }
        }
        #pragma unroll
        for (int r = 0; r < 4; r++) {
            float mx = -1e30f;
            #pragma unroll
            for (int jj = 0; jj < 5; jj++)
                if (lane + jj * 32 < JDIM) mx = fmaxf(mx, acc[r][jj]);
            #pragma unroll
            for (int o = 16; o > 0; o >>= 1)
                mx = fmaxf(mx, __shfl_xor_sync(0xffffffffu, mx, o));
            float e5[5], ssum = 0.f;
            #pragma unroll
            for (int jj = 0; jj < 5; jj++) {
                if (lane + jj * 32 < JDIM) { e5[jj] = __expf(acc[r][jj] - mx); ssum += e5[jj]; }
                else e5[jj] = 0.f;
            }
            #pragma unroll
            for (int o = 16; o > 0; o >>= 1)
                ssum += __shfl_xor_sync(0xffffffffu, ssum, o);
            float inv = 1.f / ssum;
            float* prow = g_P + ((((size_t)(b * NH + h) * NCH + n) * 64) + (i0 + r)) * JDIM;
            #pragma unroll
            for (int jj = 0; jj < 5; jj++) {
                int j = lane + jj * 32;
                if (j < JDIM) prow[j] = e5[jj] * inv;
            }
        }
    }
}

// ---------------- PV with inline head-mix ----------------
__global__ __launch_bounds__(256)
void pvmix_kernel(const float* __restrict__ nullv,
                  const float* __restrict__ Wth, const float* __restrict__ bth)
{
    extern __shared__ float sm[];
    float* mixd = sm;               // [i][j]
    float* vs   = sm + 64 * JDIM;   // [j][d]
    const int tid = threadIdx.x;
    const int n = blockIdx.x & 63;
    const int g = (blockIdx.x >> 6) & 7;
    const int b = blockIdx.x >> 9;

    if (tid < 16)
        reinterpret_cast<float4*>(vs)[tid] =
            reinterpret_cast<const float4*>(nullv + g * 64)[tid];
    const float* vsrc = g_KV + (size_t)(b * CROWS + n * 128) * 1024 + 512 + g * 64;
    for (int e = tid; e < 128 * 16; e += 256) {
        int j = e >> 4, d4 = (e & 15) << 2;
        float4 v = *reinterpret_cast<const float4*>(vsrc + (size_t)j * 1024 + d4);
        *reinterpret_cast<float4*>(vs + (j + 1) * 64 + d4) = v;
    }

    float wg[8];
    #pragma unroll
    for (int h = 0; h < 8; h++) wg[h] = __ldg(Wth + g * 8 + h);
    const float btg = __ldg(bth + g);
    const size_t hstride = (size_t)NCH * 64 * JDIM;
    const float* pbase = g_P + ((size_t)(b * NH) * NCH + n) * 64 * JDIM;
    for (int e = tid; e < 64 * JDIM; e += 256) {
        float m = btg;
        #pragma unroll
        for (int h = 0; h < 8; h++) m += wg[h] * __ldg(pbase + h * hstride + e);
        mixd[e] = m;
    }
    __syncthreads();

    const int i = tid >> 2;
    const int dbase = (tid & 3) << 4;
    float acc[16] = {};
    const float* mrow = mixd + i * JDIM;
    for (int j = 0; j < JDIM; j++) {
        float p = mrow[j];
        #pragma unroll
        for (int dd = 0; dd < 16; dd++)
            acc[dd] += p * vs[j * 64 + dbase + dd];
    }
    size_t o = ((size_t)(b * SROWS + n * 64 + i)) * DINNER + g * 64 + dbase;
    #pragma unroll
    for (int dd = 0; dd < 16; dd += 2) {
        __nv_bfloat16 h0 = __float2bfloat16(acc[dd]);
        __nv_bfloat16 h1 = __float2bfloat16(acc[dd + 1]);
        __nv_bfloat16 l0 = __float2bfloat16(acc[dd] - __bfloat162float(h0));
        __nv_bfloat16 l1 = __float2bfloat16(acc[dd + 1] - __bfloat162float(h1));
        *reinterpret_cast<__nv_bfloat162*>(g_Oh + o + dd) = __halves2bfloat162(h0, h1);
        *reinterpret_cast<__nv_bfloat162*>(g_Ol + o + dd) = __halves2bfloat162(l0, l1);
    }
}

// ---------------- zero out t=0 row ----------------
__global__ void zero_row0_kernel(float* __restrict__ out)
{
    int idx = blockIdx.x * blockDim.x + threadIdx.x;
    if (idx < BATCH * DMODEL) {
        int b = idx >> 10, d = idx & 1023;
        out[(size_t)b * 4097 * DMODEL + d] = 0.f;
    }
}

// ---------------- launch ----------------
extern "C" void kernel_launch(void* const* d_in, const int* in_sizes, int n_in,
                              void* d_out, int out_size)
{
    const float* seq   = (const float*)d_in[0];
    const float* ctx   = (const float*)d_in[1];
    const float* Wq    = (const float*)d_in[2];
    const float* Wkv   = (const float*)d_in[3];
    const float* Wout  = (const float*)d_in[4];
    const float* b_out = (const float*)d_in[5];
    const float* nullk = (const float*)d_in[6];
    const float* nullv = (const float*)d_in[7];
    const float* Wth   = (const float*)d_in[8];
    const float* bth   = (const float*)d_in[9];
    float* out = (float*)d_out;

    cudaFuncSetAttribute(mma_gemm_kernel, cudaFuncAttributeMaxDynamicSharedMemorySize, GEMM_SMEM);
    cudaFuncSetAttribute(attn_kernel,  cudaFuncAttributeMaxDynamicSharedMemorySize, 50176);
    cudaFuncSetAttribute(pvmix_kernel, cudaFuncAttributeMaxDynamicSharedMemorySize, 66048);

    __nv_bfloat16 *wq_hi, *wq_lo, *wkv_hi, *wkv_lo, *wo_hi, *wo_lo;
    __nv_bfloat16 *sh, *sl, *ch_, *cl, *oh, *ol;
    float *q32, *kv32;
    cudaGetSymbolAddress((void**)&wq_hi,  g_Wq_hi);
    cudaGetSymbolAddress((void**)&wq_lo,  g_Wq_lo);
    cudaGetSymbolAddress((void**)&wkv_hi, g_Wkv_hi);
    cudaGetSymbolAddress((void**)&wkv_lo, g_Wkv_lo);
    cudaGetSymbolAddress((void**)&wo_hi,  g_Wo_hi);
    cudaGetSymbolAddress((void**)&wo_lo,  g_Wo_lo);
    cudaGetSymbolAddress((void**)&sh,  g_Sh);
    cudaGetSymbolAddress((void**)&sl,  g_Sl);
    cudaGetSymbolAddress((void**)&ch_, g_Ch);
    cudaGetSymbolAddress((void**)&cl,  g_Cl);
    cudaGetSymbolAddress((void**)&oh,  g_Oh);
    cudaGetSymbolAddress((void**)&ol,  g_Ol);
    cudaGetSymbolAddress((void**)&q32,  g_Q);
    cudaGetSymbolAddress((void**)&kv32, g_KV);

    split_w_kernel<<<dim3(32, 32), dim3(32, 8)>>>(Wkv,  wkv_hi, wkv_lo, 1024, 1024);  // 1
    split_act_kernel<<<32768, 256>>>(ctx, ch_, cl, 2);                                // 2
    split_act_kernel<<<16384, 256>>>(seq, sh,  sl, 1);                                // 3
    // KV = pad(context) @ Wkv                                                        // 4 (profiled)
    mma_gemm_kernel<<<dim3(8, 256), 256, GEMM_SMEM>>>(ch_, cl, wkv_hi, wkv_lo, kv32,
                                                      32768, 1024, 1024, 1.0f, nullptr, 0);
    split_w_kernel<<<dim3(32, 16), dim3(32, 8)>>>(Wq,   wq_hi,  wq_lo,  1024, 512);   // 5
    // Q = (seq[:,1:] @ Wq) * 0.125                                                   // 6
    mma_gemm_kernel<<<dim3(4, 128), 256, GEMM_SMEM>>>(sh, sl, wq_hi, wq_lo, q32,
                                                      16384, 512, 1024, 0.125f, nullptr, 0);
    attn_kernel<<<BATCH * NH * NCH, 256, 50176>>>(nullk);                             // 7
    pvmix_kernel<<<BATCH * NH * NCH, 256, 66048>>>(nullv, Wth, bth);                  // 8
    split_w_kernel<<<dim3(16, 32), dim3(32, 8)>>>(Wout, wo_hi,  wo_lo,  512, 1024);   // 9
    // out = O @ Wout + b_out, scattered to d_out rows t=1..4096                      // 10
    mma_gemm_kernel<<<dim3(8, 128), 256, GEMM_SMEM>>>(oh, ol, wo_hi, wo_lo, out,
                                                      16384, 1024, 512, 1.0f, b_out, 2);
    zero_row0_kernel<<<4, 1024>>>(out);                                               // 11
}

// round 8
// speedup vs baseline: 2.1848x; 1.2876x over previous
#include <cuda_runtime.h>
#include <cuda_fp16.h>
#include <cstdint>
#include <math.h>

// ---------------- problem constants ----------------
#define BATCH  4
#define NH     8
#define NCH    64
#define SROWS  4096
#define CROWS  8192
#define DMODEL 1024
#define DINNER 512
#define JDIM   129

// ---------------- scratch (device globals; no allocation) ----------------
__device__ float g_Q [(size_t)BATCH * SROWS * DINNER];
__device__ float g_KV[(size_t)BATCH * CROWS * 1024];
__device__ float g_P [(size_t)BATCH * NH * NCH * 64 * JDIM];

// fp16 activations (single precision plane)
__device__ __half g_Sh[(size_t)16384 * 1024];   // seq rows remapped
__device__ __half g_Ch[(size_t)32768 * 1024];   // ctx rows padded
__device__ __half g_Oh[(size_t)16384 * 512];    // attention out

// fp16 weights, hi/lo split, transposed to [N][K]
__device__ __half g_Wq_hi [1024 * 512];
__device__ __half g_Wq_lo [1024 * 512];
__device__ __half g_Wkv_hi[1024 * 1024];
__device__ __half g_Wkv_lo[1024 * 1024];
__device__ __half g_Wo_hi [512 * 1024];
__device__ __half g_Wo_lo [512 * 1024];

// ---------------- asm helpers ----------------
__device__ __forceinline__ uint32_t smem_u32(const void* p) {
    uint32_t a;
    asm("{ .reg .u64 t; cvta.to.shared.u64 t, %1; cvt.u32.u64 %0, t; }" : "=r"(a) : "l"(p));
    return a;
}
#define CP_ASYNC16(dst, src) \
    asm volatile("cp.async.cg.shared.global [%0], [%1], 16;" :: "r"(dst), "l"(src))
#define CP_COMMIT() asm volatile("cp.async.commit_group;" ::: "memory")
#define CP_WAIT(n)  asm volatile("cp.async.wait_group %0;" :: "n"(n) : "memory")

#define LDSM_X4(r, addr) \
    asm volatile("ldmatrix.sync.aligned.m8n8.x4.shared.b16 {%0,%1,%2,%3}, [%4];" \
        : "=r"((r)[0]), "=r"((r)[1]), "=r"((r)[2]), "=r"((r)[3]) : "r"(addr))

__device__ __forceinline__ void mma_f16(float* c, const uint32_t* a, uint32_t b0, uint32_t b1) {
    asm volatile("mma.sync.aligned.m16n8k16.row.col.f32.f16.f16.f32 "
                 "{%0,%1,%2,%3}, {%4,%5,%6,%7}, {%8,%9}, {%0,%1,%2,%3};"
                 : "+f"(c[0]), "+f"(c[1]), "+f"(c[2]), "+f"(c[3])
                 : "r"(a[0]), "r"(a[1]), "r"(a[2]), "r"(a[3]), "r"(b0), "r"(b1));
}

// ---------------- weight split: W[K,N] fp32 -> Whi/Wlo[N,K] fp16 ----------------
__global__ void split_w_kernel(const float* __restrict__ W,
                               __half* __restrict__ Whi,
                               __half* __restrict__ Wlo, int K, int N)
{
    __shared__ float t[32][33];
    int kb = blockIdx.x * 32, nb = blockIdx.y * 32;
    int x = threadIdx.x, y = threadIdx.y;
    for (int i = y; i < 32; i += 8)
        t[i][x] = W[(size_t)(kb + i) * N + nb + x];
    __syncthreads();
    for (int i = y; i < 32; i += 8) {
        float w = t[x][i];
        __half h = __float2half(w);
        __half l = __float2half(w - __half2float(h));
        size_t o = (size_t)(nb + i) * K + kb + x;
        Whi[o] = h; Wlo[o] = l;
    }
}

// ---------------- activation convert: fp32 rows -> fp16 [M][1024] ----------------
// mode 1: seq remap (row -> seq[b, t+1]); mode 2: ctx pad (first 127 rows zero)
__global__ __launch_bounds__(256)
void split_act_kernel(const float* __restrict__ src, __half* __restrict__ Dh, int mode)
{
    size_t idx = (size_t)blockIdx.x * 256 + threadIdx.x;
    int row = (int)(idx >> 8), f4 = (int)(idx & 255);
    const float* p;
    if (mode == 1) { int b = row >> 12, t = row & 4095; p = src + ((size_t)b * 4097 + t + 1) * 1024; }
    else           { int b = row >> 13, r = row & 8191;
                     p = (r < 127) ? nullptr : src + ((size_t)b * 8065 + (r - 127)) * 1024; }
    float4 v = p ? *reinterpret_cast<const float4*>(p + f4 * 4) : make_float4(0.f, 0.f, 0.f, 0.f);
    size_t o = (size_t)row * 1024 + f4 * 4;
    *reinterpret_cast<__half2*>(Dh + o)     = __floats2half2_rn(v.x, v.y);
    *reinterpret_cast<__half2*>(Dh + o + 2) = __floats2half2_rn(v.z, v.w);
}

// ---------------- fp16x2 mma.sync GEMM: CTA 128x128, warp 64x32, BK=32, 2 CTAs/SM ----------------
// C = A(fp16) * (Bhi + Blo)^T, fp32 accum. smem stage 32KB:
//  A region 16KB: row 128B = [ah k0..31 | unused], chunks 0-3 used
//  B region 16KB: row 128B = [bh k0..31 | bl k0..31]
// 16B-chunk XOR-8 swizzle. 3-stage cp.async pipeline, single barrier per k-iter.
#define GSTG 32768
#define GEMM_SMEM (3 * GSTG)

__global__ __launch_bounds__(256, 2)
void mma_gemm_kernel(const __half* __restrict__ Ah,
                     const __half* __restrict__ Bh, const __half* __restrict__ Bl,
                     float* __restrict__ C, int M, int N, int K,
                     float alpha, const float* __restrict__ bias, int c_mode)
{
    extern __shared__ char smem[];
    const uint32_t sbase = smem_u32(smem);
    const int tid = threadIdx.x, warp = tid >> 5, lane = tid & 31;
    const int bn = blockIdx.x, bm = blockIdx.y;
    const int warp_m = warp >> 2, warp_n = warp & 3;
    const int KT = K >> 5;

    // cp.async mapping: 1536 16B chunks per stage, 6 per thread
    const __half* ld_src[6];
    uint32_t ld_dst[6];
    #pragma unroll
    for (int c = 0; c < 6; c++) {
        int idx = (c << 8) + tid;               // 0..1535
        if (idx < 512) {                        // A: 128 rows x 4 chunks (hi only)
            int row = idx >> 2, ch = idx & 3;
            ld_src[c] = Ah + (size_t)(bm * 128 + row) * K + ch * 8;
            ld_dst[c] = sbase + row * 128 + ((ch ^ (row & 7)) << 4);
        } else {                                // B: 128 rows x 8 chunks (hi|lo)
            int id = idx - 512;
            int row = id >> 3, ch = id & 7;
            ld_src[c] = ((ch < 4) ? Bh : Bl) + (size_t)(bn * 128 + row) * K + (ch & 3) * 8;
            ld_dst[c] = sbase + 16384 + row * 128 + ((ch ^ (row & 7)) << 4);
        }
    }

    auto issue_stage = [&](int kt, int s) {
        #pragma unroll
        for (int c = 0; c < 6; c++)
            CP_ASYNC16(ld_dst[c] + s * GSTG, ld_src[c] + kt * 32);
    };

    float acc[4][4][4] = {};

    const int rlaneA = (lane & 7) + (((lane >> 3) & 1) << 3);
    const int khalfA = (lane >> 4) & 1;
    const int rlaneB = (lane & 7) + (((lane >> 4) & 1) << 3);
    const int khalfB = (lane >> 3) & 1;

    issue_stage(0, 0); CP_COMMIT();
    if (KT > 1) issue_stage(1, 1);
    CP_COMMIT();

    for (int kt = 0; kt < KT; kt++) {
        const int s = kt % 3;
        CP_WAIT(1);
        __syncthreads();      // single barrier: also protects buffer (kt+2)%3 == (kt-1)%3 reuse
        if (kt + 2 < KT) issue_stage(kt + 2, (kt + 2) % 3);
        CP_COMMIT();

        const uint32_t sA = sbase + s * GSTG;
        const uint32_t sB = sA + 16384;
        #pragma unroll
        for (int kk = 0; kk < 2; kk++) {
            uint32_t aH[4][4];
            #pragma unroll
            for (int mf = 0; mf < 4; mf++) {
                int r = warp_m * 64 + mf * 16 + rlaneA;
                int ch = kk * 2 + khalfA;
                LDSM_X4(aH[mf], sA + r * 128 + ((ch ^ (r & 7)) << 4));
            }
            #pragma unroll
            for (int p = 0; p < 2; p++) {
                uint32_t bH[4], bL[4];
                int r = warp_n * 32 + p * 16 + rlaneB;
                int ch = kk * 2 + khalfB;
                LDSM_X4(bH, sB + r * 128 + (((ch)     ^ (r & 7)) << 4));
                LDSM_X4(bL, sB + r * 128 + (((ch + 4) ^ (r & 7)) << 4));
                #pragma unroll
                for (int q = 0; q < 2; q++) {
                    const int nf = p * 2 + q;
                    uint32_t b0h = bH[q * 2], b1h = bH[q * 2 + 1];
                    uint32_t b0l = bL[q * 2], b1l = bL[q * 2 + 1];
                    #pragma unroll
                    for (int mf = 0; mf < 4; mf++) {
                        mma_f16(acc[mf][nf], aH[mf], b0h, b1h);
                        mma_f16(acc[mf][nf], aH[mf], b0l, b1l);
                    }
                }
            }
        }
    }

    const int row_in = lane >> 2;
    const int col_in = (lane & 3) * 2;
    #pragma unroll
    for (int mf = 0; mf < 4; mf++) {
        int r0 = bm * 128 + warp_m * 64 + mf * 16 + row_in;
        float *p0, *p1;
        if (c_mode == 2) {
            int b0 = r0 >> 12, t0 = r0 & 4095;
            int r1 = r0 + 8, b1 = r1 >> 12, t1 = r1 & 4095;
            p0 = C + ((size_t)b0 * 4097 + t0 + 1) * N;
            p1 = C + ((size_t)b1 * 4097 + t1 + 1) * N;
        } else {
            p0 = C + (size_t)r0 * N;
            p1 = p0 + (size_t)8 * N;
        }
        #pragma unroll
        for (int nf = 0; nf < 4; nf++) {
            int c0 = bn * 128 + warp_n * 32 + nf * 8 + col_in;
            float bx = 0.f, by = 0.f;
            if (bias) { float2 bv = *reinterpret_cast<const float2*>(bias + c0); bx = bv.x; by = bv.y; }
            float2 v0, v1;
            v0.x = alpha * acc[mf][nf][0] + bx; v0.y = alpha * acc[mf][nf][1] + by;
            v1.x = alpha * acc[mf][nf][2] + bx; v1.y = alpha * acc[mf][nf][3] + by;
            *reinterpret_cast<float2*>(p0 + c0) = v0;
            *reinterpret_cast<float2*>(p1 + c0) = v1;
        }
    }
}

// ---------------- sim + softmax per (b, h, chunk); P fp32 ----------------
__global__ __launch_bounds__(256)
void attn_kernel(const float* __restrict__ nullk)
{
    extern __shared__ float sm[];
    float* qs = sm;
    float* ks = sm + 64 * 64;
    const int tid = threadIdx.x;
    const int n = blockIdx.x & 63;
    const int h = (blockIdx.x >> 6) & 7;
    const int b = blockIdx.x >> 9;

    const float* qsrc = g_Q + ((size_t)(b * SROWS + n * 64)) * DINNER + h * 64;
    for (int t = tid; t < 1024; t += 256) {
        int i = t >> 4, d4 = (t & 15) << 2;
        float4 v = *reinterpret_cast<const float4*>(qsrc + (size_t)i * DINNER + d4);
        qs[i * 64 + d4 + 0] = v.x;
        qs[i * 64 + d4 + 1] = v.y;
        qs[i * 64 + d4 + 2] = v.z;
        qs[i * 64 + d4 + 3] = v.w;
    }
    if (tid < 64) ks[tid * 132 + 0] = nullk[h * 64 + tid];
    const float* ksrc = g_KV + (size_t)(b * CROWS + n * 128) * 1024 + h * 64;
    for (int e = tid; e < 128 * 64; e += 256) {
        int j = e >> 6, d = e & 63;
        ks[d * 132 + j + 1] = ksrc[(size_t)j * 1024 + d];
    }
    __syncthreads();

    const int warp = tid >> 5, lane = tid & 31;
    #pragma unroll
    for (int grp = 0; grp < 2; grp++) {
        const int i0 = warp * 8 + grp * 4;
        float acc[4][5] = {};
        #pragma unroll 4
        for (int d = 0; d < 64; d++) {
            float kv[5];
            #pragma unroll
            for (int jj = 0; jj < 5; jj++) {
                int j = lane + jj * 32;
                kv[jj] = (j < JDIM) ? ks[d * 132 + j] : 0.f;
            }
            #pragma unroll
            for (int r = 0; r < 4; r++) {
                float qv = qs[(i0 + r) * 64 + d];
                #pragma unroll
                for (int jj = 0; jj < 5; jj++) acc[r][jj] += qv * kv[jj];
            }
        }
        #pragma unroll
        for (int r = 0; r < 4; r++) {
            float mx = -1e30f;
            #pragma unroll
            for (int jj = 0; jj < 5; jj++)
                if (lane + jj * 32 < JDIM) mx = fmaxf(mx, acc[r][jj]);
            #pragma unroll
            for (int o = 16; o > 0; o >>= 1)
                mx = fmaxf(mx, __shfl_xor_sync(0xffffffffu, mx, o));
            float e5[5], ssum = 0.f;
            #pragma unroll
            for (int jj = 0; jj < 5; jj++) {
                if (lane + jj * 32 < JDIM) { e5[jj] = __expf(acc[r][jj] - mx); ssum += e5[jj]; }
                else e5[jj] = 0.f;
            }
            #pragma unroll
            for (int o = 16; o > 0; o >>= 1)
                ssum += __shfl_xor_sync(0xffffffffu, ssum, o);
            float inv = 1.f / ssum;
            float* prow = g_P + ((((size_t)(b * NH + h) * NCH + n) * 64) + (i0 + r)) * JDIM;
            #pragma unroll
            for (int jj = 0; jj < 5; jj++) {
                int j = lane + jj * 32;
                if (j < JDIM) prow[j] = e5[jj] * inv;
            }
        }
    }
}

// ---------------- PV with inline head-mix; writes fp16 O ----------------
__global__ __launch_bounds__(256)
void pvmix_kernel(const float* __restrict__ nullv,
                  const float* __restrict__ Wth, const float* __restrict__ bth)
{
    extern __shared__ float sm[];
    float* mixd = sm;               // [i][j]
    float* vs   = sm + 64 * JDIM;   // [j][d]
    const int tid = threadIdx.x;
    const int n = blockIdx.x & 63;
    const int g = (blockIdx.x >> 6) & 7;
    const int b = blockIdx.x >> 9;

    if (tid < 16)
        reinterpret_cast<float4*>(vs)[tid] =
            reinterpret_cast<const float4*>(nullv + g * 64)[tid];
    const float* vsrc = g_KV + (size_t)(b * CROWS + n * 128) * 1024 + 512 + g * 64;
    for (int e = tid; e < 128 * 16; e += 256) {
        int j = e >> 4, d4 = (e & 15) << 2;
        float4 v = *reinterpret_cast<const float4*>(vsrc + (size_t)j * 1024 + d4);
        *reinterpret_cast<float4*>(vs + (j + 1) * 64 + d4) = v;
    }

    float wg[8];
    #pragma unroll
    for (int h = 0; h < 8; h++) wg[h] = __ldg(Wth + g * 8 + h);
    const float btg = __ldg(bth + g);
    const size_t hstride = (size_t)NCH * 64 * JDIM;
    const float* pbase = g_P + ((size_t)(b * NH) * NCH + n) * 64 * JDIM;
    for (int e = tid; e < 64 * JDIM; e += 256) {
        float m = btg;
        #pragma unroll
        for (int h = 0; h < 8; h++) m += wg[h] * __ldg(pbase + h * hstride + e);
        mixd[e] = m;
    }
    __syncthreads();

    const int i = tid >> 2;
    const int dbase = (tid & 3) << 4;
    float acc[16] = {};
    const float* mrow = mixd + i * JDIM;
    for (int j = 0; j < JDIM; j++) {
        float p = mrow[j];
        #pragma unroll
        for (int dd = 0; dd < 16; dd++)
            acc[dd] += p * vs[j * 64 + dbase + dd];
    }
    size_t o = ((size_t)(b * SROWS + n * 64 + i)) * DINNER + g * 64 + dbase;
    #pragma unroll
    for (int dd = 0; dd < 16; dd += 2)
        *reinterpret_cast<__half2*>(g_Oh + o + dd) = __floats2half2_rn(acc[dd], acc[dd + 1]);
}

// ---------------- zero out t=0 row ----------------
__global__ void zero_row0_kernel(float* __restrict__ out)
{
    int idx = blockIdx.x * blockDim.x + threadIdx.x;
    if (idx < BATCH * DMODEL) {
        int b = idx >> 10, d = idx & 1023;
        out[(size_t)b * 4097 * DMODEL + d] = 0.f;
    }
}

// ---------------- launch ----------------
extern "C" void kernel_launch(void* const* d_in, const int* in_sizes, int n_in,
                              void* d_out, int out_size)
{
    const float* seq   = (const float*)d_in[0];
    const float* ctx   = (const float*)d_in[1];
    const float* Wq    = (const float*)d_in[2];
    const float* Wkv   = (const float*)d_in[3];
    const float* Wout  = (const float*)d_in[4];
    const float* b_out = (const float*)d_in[5];
    const float* nullk = (const float*)d_in[6];
    const float* nullv = (const float*)d_in[7];
    const float* Wth   = (const float*)d_in[8];
    const float* bth   = (const float*)d_in[9];
    float* out = (float*)d_out;

    cudaFuncSetAttribute(mma_gemm_kernel, cudaFuncAttributeMaxDynamicSharedMemorySize, GEMM_SMEM);
    cudaFuncSetAttribute(attn_kernel,  cudaFuncAttributeMaxDynamicSharedMemorySize, 50176);
    cudaFuncSetAttribute(pvmix_kernel, cudaFuncAttributeMaxDynamicSharedMemorySize, 66048);

    __half *wq_hi, *wq_lo, *wkv_hi, *wkv_lo, *wo_hi, *wo_lo;
    __half *sh, *ch_, *oh;
    float *q32, *kv32;
    cudaGetSymbolAddress((void**)&wq_hi,  g_Wq_hi);
    cudaGetSymbolAddress((void**)&wq_lo,  g_Wq_lo);
    cudaGetSymbolAddress((void**)&wkv_hi, g_Wkv_hi);
    cudaGetSymbolAddress((void**)&wkv_lo, g_Wkv_lo);
    cudaGetSymbolAddress((void**)&wo_hi,  g_Wo_hi);
    cudaGetSymbolAddress((void**)&wo_lo,  g_Wo_lo);
    cudaGetSymbolAddress((void**)&sh,  g_Sh);
    cudaGetSymbolAddress((void**)&ch_, g_Ch);
    cudaGetSymbolAddress((void**)&oh,  g_Oh);
    cudaGetSymbolAddress((void**)&q32,  g_Q);
    cudaGetSymbolAddress((void**)&kv32, g_KV);

    split_w_kernel<<<dim3(32, 32), dim3(32, 8)>>>(Wkv,  wkv_hi, wkv_lo, 1024, 1024);  // 1
    split_act_kernel<<<32768, 256>>>(ctx, ch_, 2);                                    // 2
    split_act_kernel<<<16384, 256>>>(seq, sh,  1);                                    // 3
    // KV = pad(context) @ Wkv                                                        // 4 (profiled)
    mma_gemm_kernel<<<dim3(8, 256), 256, GEMM_SMEM>>>(ch_, wkv_hi, wkv_lo, kv32,
                                                      32768, 1024, 1024, 1.0f, nullptr, 0);
    split_w_kernel<<<dim3(32, 16), dim3(32, 8)>>>(Wq,   wq_hi,  wq_lo,  1024, 512);   // 5
    // Q = (seq[:,1:] @ Wq) * 0.125                                                   // 6
    mma_gemm_kernel<<<dim3(4, 128), 256, GEMM_SMEM>>>(sh, wq_hi, wq_lo, q32,
                                                      16384, 512, 1024, 0.125f, nullptr, 0);
    attn_kernel<<<BATCH * NH * NCH, 256, 50176>>>(nullk);                             // 7
    pvmix_kernel<<<BATCH * NH * NCH, 256, 66048>>>(nullv, Wth, bth);                  // 8
    split_w_kernel<<<dim3(16, 32), dim3(32, 8)>>>(Wout, wo_hi,  wo_lo,  512, 1024);   // 9
    // out = O @ Wout + b_out, scattered to d_out rows t=1..4096                      // 10
    mma_gemm_kernel<<<dim3(8, 128), 256, GEMM_SMEM>>>(oh, wo_hi, wo_lo, out,
                                                      16384, 1024, 512, 1.0f, b_out, 2);
    zero_row0_kernel<<<4, 1024>>>(out);                                               // 11
}

// round 9
// speedup vs baseline: 2.2857x; 1.0462x over previous
#include <cuda_runtime.h>
#include <cuda_fp16.h>
#include <cstdint>
#include <math.h>

// ---------------- problem constants ----------------
#define BATCH  4
#define NH     8
#define NCH    64
#define SROWS  4096
#define CROWS  8192
#define DMODEL 1024
#define DINNER 512
#define JDIM   129

// ---------------- scratch (device globals; no allocation) ----------------
__device__ float  g_Q [(size_t)BATCH * SROWS * DINNER];
__device__ float  g_KV[(size_t)BATCH * CROWS * 1024];
__device__ __half g_P [(size_t)BATCH * NH * NCH * 64 * JDIM];

// fp16 activations (single precision plane)
__device__ __half g_Sh[(size_t)16384 * 1024];
__device__ __half g_Ch[(size_t)32768 * 1024];
__device__ __half g_Oh[(size_t)16384 * 512];

// fp16 weights: hi plane at [0, N*K), lo plane at [N*K, 2*N*K), each [N][K]
__device__ __half g_Wq [(size_t)2 * 1024 * 512];
__device__ __half g_Wkv[(size_t)2 * 1024 * 1024];
__device__ __half g_Wo [(size_t)2 * 512 * 1024];

// ---------------- asm helpers ----------------
__device__ __forceinline__ uint32_t smem_u32(const void* p) {
    uint32_t a;
    asm("{ .reg .u64 t; cvta.to.shared.u64 t, %1; cvt.u32.u64 %0, t; }" : "=r"(a) : "l"(p));
    return a;
}
#define CP_ASYNC16(dst, src) \
    asm volatile("cp.async.cg.shared.global [%0], [%1], 16;" :: "r"(dst), "l"(src))
#define CP_COMMIT() asm volatile("cp.async.commit_group;" ::: "memory")
#define CP_WAIT(n)  asm volatile("cp.async.wait_group %0;" :: "n"(n) : "memory")

#define LDSM_X4(r, addr) \
    asm volatile("ldmatrix.sync.aligned.m8n8.x4.shared.b16 {%0,%1,%2,%3}, [%4];" \
        : "=r"((r)[0]), "=r"((r)[1]), "=r"((r)[2]), "=r"((r)[3]) : "r"(addr))

__device__ __forceinline__ void mma_f16(float* c, const uint32_t* a, uint32_t b0, uint32_t b1) {
    asm volatile("mma.sync.aligned.m16n8k16.row.col.f32.f16.f16.f32 "
                 "{%0,%1,%2,%3}, {%4,%5,%6,%7}, {%8,%9}, {%0,%1,%2,%3};"
                 : "+f"(c[0]), "+f"(c[1]), "+f"(c[2]), "+f"(c[3])
                 : "r"(a[0]), "r"(a[1]), "r"(a[2]), "r"(a[3]), "r"(b0), "r"(b1));
}

// ---------------- weight split: W[K,N] fp32 -> hi/lo fp16 planes [N][K] ----------------
__global__ void split_w_kernel(const float* __restrict__ W,
                               __half* __restrict__ Wp, int K, int N)
{
    __shared__ float t[32][33];
    int kb = blockIdx.x * 32, nb = blockIdx.y * 32;
    int x = threadIdx.x, y = threadIdx.y;
    const size_t plane = (size_t)N * K;
    for (int i = y; i < 32; i += 8)
        t[i][x] = W[(size_t)(kb + i) * N + nb + x];
    __syncthreads();
    for (int i = y; i < 32; i += 8) {
        float w = t[x][i];
        __half h = __float2half(w);
        __half l = __float2half(w - __half2float(h));
        size_t o = (size_t)(nb + i) * K + kb + x;
        Wp[o] = h; Wp[o + plane] = l;
    }
}

// ---------------- activation convert: fp32 rows -> fp16 [M][1024] ----------------
__global__ __launch_bounds__(256)
void split_act_kernel(const float* __restrict__ src, __half* __restrict__ Dh, int mode)
{
    size_t idx = (size_t)blockIdx.x * 256 + threadIdx.x;
    int row = (int)(idx >> 8), f4 = (int)(idx & 255);
    const float* p;
    if (mode == 1) { int b = row >> 12, t = row & 4095; p = src + ((size_t)b * 4097 + t + 1) * 1024; }
    else           { int b = row >> 13, r = row & 8191;
                     p = (r < 127) ? nullptr : src + ((size_t)b * 8065 + (r - 127)) * 1024; }
    float4 v = p ? *reinterpret_cast<const float4*>(p + f4 * 4) : make_float4(0.f, 0.f, 0.f, 0.f);
    size_t o = (size_t)row * 1024 + f4 * 4;
    *reinterpret_cast<__half2*>(Dh + o)     = __floats2half2_rn(v.x, v.y);
    *reinterpret_cast<__half2*>(Dh + o + 2) = __floats2half2_rn(v.z, v.w);
}

// ---------------- fp16x2 mma.sync GEMM: CTA 128x128, warp 64x32, BK=64, 2-stage ----------------
// stage 48KB: A 16KB (128 rows x 128B = k0..63 hi), B 32KB (128 rows x 256B = [hi k0..63 | lo k0..63])
// 16B-chunk XOR-8 swizzle per 128B half-row. loOff = N*K (element offset of lo plane).
#define GSTG 49152
#define GEMM_SMEM (2 * GSTG)

__global__ __launch_bounds__(256, 2)
void mma_gemm_kernel(const __half* __restrict__ Ah,
                     const __half* __restrict__ Bp, uint32_t loOff,
                     float* __restrict__ C, int M, int N, int K,
                     float alpha, const float* __restrict__ bias, int c_mode)
{
    extern __shared__ char smem[];
    const uint32_t sbase = smem_u32(smem);
    const int tid = threadIdx.x, warp = tid >> 5, lane = tid & 31;
    const int bn = blockIdx.x, bm = blockIdx.y;
    const int warp_m = warp >> 2, warp_n = warp & 3;
    const int KT = K >> 6;

    // A: 1024 chunks -> 4/thread; B: 2048 chunks -> 8/thread
    uint32_t aoff[4], adst[4], boff[8], bdst[8];
    #pragma unroll
    for (int c = 0; c < 4; c++) {
        int idx = (c << 8) + tid;
        int row = idx >> 3, ch = idx & 7;
        aoff[c] = (uint32_t)(bm * 128 + row) * (uint32_t)K + ch * 8;
        adst[c] = sbase + row * 128 + ((ch ^ (row & 7)) << 4);
    }
    #pragma unroll
    for (int c = 0; c < 8; c++) {
        int idx = (c << 8) + tid;
        int row = idx >> 4, ch = idx & 15;
        int lo = ch >> 3, c8 = ch & 7;
        boff[c] = (uint32_t)(bn * 128 + row) * (uint32_t)K + c8 * 8 + (lo ? loOff : 0u);
        bdst[c] = sbase + 16384 + row * 256 + lo * 128 + ((c8 ^ (row & 7)) << 4);
    }

    auto issue_stage = [&](int kt, int s) {
        const uint32_t koff = (uint32_t)kt << 6;
        const uint32_t sd = (uint32_t)s * GSTG;
        #pragma unroll
        for (int c = 0; c < 4; c++) CP_ASYNC16(adst[c] + sd, Ah + aoff[c] + koff);
        #pragma unroll
        for (int c = 0; c < 8; c++) CP_ASYNC16(bdst[c] + sd, Bp + boff[c] + koff);
    };

    float acc[4][4][4] = {};

    const int rlaneA = (lane & 7) + (((lane >> 3) & 1) << 3);
    const int khalfA = (lane >> 4) & 1;
    const int rlaneB = (lane & 7) + (((lane >> 4) & 1) << 3);
    const int khalfB = (lane >> 3) & 1;

    issue_stage(0, 0); CP_COMMIT();

    for (int kt = 0; kt < KT; kt++) {
        const int s = kt & 1;
        CP_WAIT(0);
        __syncthreads();   // all reads of buffer s^1 (iter kt-1) done before refilling it
        if (kt + 1 < KT) { issue_stage(kt + 1, s ^ 1); CP_COMMIT(); }

        const uint32_t sA = sbase + s * GSTG;
        const uint32_t sB = sA + 16384;
        #pragma unroll
        for (int kk = 0; kk < 4; kk++) {
            uint32_t aH[4][4];
            #pragma unroll
            for (int mf = 0; mf < 4; mf++) {
                int r = warp_m * 64 + mf * 16 + rlaneA;
                int ch = kk * 2 + khalfA;
                LDSM_X4(aH[mf], sA + r * 128 + ((ch ^ (r & 7)) << 4));
            }
            #pragma unroll
            for (int p = 0; p < 2; p++) {
                uint32_t bH[4], bL[4];
                int r = warp_n * 32 + p * 16 + rlaneB;
                int ch = kk * 2 + khalfB;
                LDSM_X4(bH, sB + r * 256 +       ((ch ^ (r & 7)) << 4));
                LDSM_X4(bL, sB + r * 256 + 128 + ((ch ^ (r & 7)) << 4));
                #pragma unroll
                for (int q = 0; q < 2; q++) {
                    const int nf = p * 2 + q;
                    uint32_t b0h = bH[q * 2], b1h = bH[q * 2 + 1];
                    uint32_t b0l = bL[q * 2], b1l = bL[q * 2 + 1];
                    #pragma unroll
                    for (int mf = 0; mf < 4; mf++) {
                        mma_f16(acc[mf][nf], aH[mf], b0h, b1h);
                        mma_f16(acc[mf][nf], aH[mf], b0l, b1l);
                    }
                }
            }
        }
    }

    const int row_in = lane >> 2;
    const int col_in = (lane & 3) * 2;
    #pragma unroll
    for (int mf = 0; mf < 4; mf++) {
        int r0 = bm * 128 + warp_m * 64 + mf * 16 + row_in;
        float *p0, *p1;
        if (c_mode == 2) {
            int b0 = r0 >> 12, t0 = r0 & 4095;
            int r1 = r0 + 8, b1 = r1 >> 12, t1 = r1 & 4095;
            p0 = C + ((size_t)b0 * 4097 + t0 + 1) * N;
            p1 = C + ((size_t)b1 * 4097 + t1 + 1) * N;
        } else {
            p0 = C + (size_t)r0 * N;
            p1 = p0 + (size_t)8 * N;
        }
        #pragma unroll
        for (int nf = 0; nf < 4; nf++) {
            int c0 = bn * 128 + warp_n * 32 + nf * 8 + col_in;
            float bx = 0.f, by = 0.f;
            if (bias) { float2 bv = *reinterpret_cast<const float2*>(bias + c0); bx = bv.x; by = bv.y; }
            float2 v0, v1;
            v0.x = alpha * acc[mf][nf][0] + bx; v0.y = alpha * acc[mf][nf][1] + by;
            v1.x = alpha * acc[mf][nf][2] + bx; v1.y = alpha * acc[mf][nf][3] + by;
            *reinterpret_cast<float2*>(p0 + c0) = v0;
            *reinterpret_cast<float2*>(p1 + c0) = v1;
        }
    }
}

// ---------------- sim + softmax per (b, h, chunk); P stored fp16 ----------------
__global__ __launch_bounds__(256)
void attn_kernel(const float* __restrict__ nullk)
{
    extern __shared__ float sm[];
    float* qs = sm;
    float* ks = sm + 64 * 64;
    const int tid = threadIdx.x;
    const int n = blockIdx.x & 63;
    const int h = (blockIdx.x >> 6) & 7;
    const int b = blockIdx.x >> 9;

    const float* qsrc = g_Q + ((size_t)(b * SROWS + n * 64)) * DINNER + h * 64;
    for (int t = tid; t < 1024; t += 256) {
        int i = t >> 4, d4 = (t & 15) << 2;
        float4 v = *reinterpret_cast<const float4*>(qsrc + (size_t)i * DINNER + d4);
        qs[i * 64 + d4 + 0] = v.x;
        qs[i * 64 + d4 + 1] = v.y;
        qs[i * 64 + d4 + 2] = v.z;
        qs[i * 64 + d4 + 3] = v.w;
    }
    if (tid < 64) ks[tid * 132 + 0] = nullk[h * 64 + tid];
    const float* ksrc = g_KV + (size_t)(b * CROWS + n * 128) * 1024 + h * 64;
    for (int e = tid; e < 128 * 64; e += 256) {
        int j = e >> 6, d = e & 63;
        ks[d * 132 + j + 1] = ksrc[(size_t)j * 1024 + d];
    }
    __syncthreads();

    const int warp = tid >> 5, lane = tid & 31;
    #pragma unroll
    for (int grp = 0; grp < 2; grp++) {
        const int i0 = warp * 8 + grp * 4;
        float acc[4][5] = {};
        #pragma unroll 4
        for (int d = 0; d < 64; d++) {
            float kv[5];
            #pragma unroll
            for (int jj = 0; jj < 5; jj++) {
                int j = lane + jj * 32;
                kv[jj] = (j < JDIM) ? ks[d * 132 + j] : 0.f;
            }
            #pragma unroll
            for (int r = 0; r < 4; r++) {
                float qv = qs[(i0 + r) * 64 + d];
                #pragma unroll
                for (int jj = 0; jj < 5; jj++) acc[r][jj] += qv * kv[jj];
            }
        }
        #pragma unroll
        for (int r = 0; r < 4; r++) {
            float mx = -1e30f;
            #pragma unroll
            for (int jj = 0; jj < 5; jj++)
                if (lane + jj * 32 < JDIM) mx = fmaxf(mx, acc[r][jj]);
            #pragma unroll
            for (int o = 16; o > 0; o >>= 1)
                mx = fmaxf(mx, __shfl_xor_sync(0xffffffffu, mx, o));
            float e5[5], ssum = 0.f;
            #pragma unroll
            for (int jj = 0; jj < 5; jj++) {
                if (lane + jj * 32 < JDIM) { e5[jj] = __expf(acc[r][jj] - mx); ssum += e5[jj]; }
                else e5[jj] = 0.f;
            }
            #pragma unroll
            for (int o = 16; o > 0; o >>= 1)
                ssum += __shfl_xor_sync(0xffffffffu, ssum, o);
            float inv = 1.f / ssum;
            __half* prow = g_P + ((((size_t)(b * NH + h) * NCH + n) * 64) + (i0 + r)) * JDIM;
            #pragma unroll
            for (int jj = 0; jj < 5; jj++) {
                int j = lane + jj * 32;
                if (j < JDIM) prow[j] = __float2half(e5[jj] * inv);
            }
        }
    }
}

// ---------------- PV with inline head-mix (fp16 P, half2 reads); writes fp16 O ----------------
__global__ __launch_bounds__(256)
void pvmix_kernel(const float* __restrict__ nullv,
                  const float* __restrict__ Wth, const float* __restrict__ bth)
{
    extern __shared__ float sm[];
    float* mixd = sm;               // [i][j]
    float* vs   = sm + 64 * JDIM;   // [j][d]
    const int tid = threadIdx.x;
    const int n = blockIdx.x & 63;
    const int g = (blockIdx.x >> 6) & 7;
    const int b = blockIdx.x >> 9;

    if (tid < 16)
        reinterpret_cast<float4*>(vs)[tid] =
            reinterpret_cast<const float4*>(nullv + g * 64)[tid];
    const float* vsrc = g_KV + (size_t)(b * CROWS + n * 128) * 1024 + 512 + g * 64;
    for (int e = tid; e < 128 * 16; e += 256) {
        int j = e >> 4, d4 = (e & 15) << 2;
        float4 v = *reinterpret_cast<const float4*>(vsrc + (size_t)j * 1024 + d4);
        *reinterpret_cast<float4*>(vs + (j + 1) * 64 + d4) = v;
    }

    float wg[8];
    #pragma unroll
    for (int h = 0; h < 8; h++) wg[h] = __ldg(Wth + g * 8 + h);
    const float btg = __ldg(bth + g);
    const size_t hstride2 = ((size_t)NCH * 64 * JDIM) >> 1;   // in half2
    const __half2* pb2 = reinterpret_cast<const __half2*>(
        g_P + ((size_t)(b * NH) * NCH + n) * 64 * JDIM);
    for (int e2 = tid; e2 < (64 * JDIM) / 2; e2 += 256) {
        float mx = btg, my = btg;
        #pragma unroll
        for (int h = 0; h < 8; h++) {
            float2 pf = __half22float2(__ldg(pb2 + h * hstride2 + e2));
            mx += wg[h] * pf.x;
            my += wg[h] * pf.y;
        }
        mixd[2 * e2]     = mx;
        mixd[2 * e2 + 1] = my;
    }
    __syncthreads();

    const int i = tid >> 2;
    const int dbase = (tid & 3) << 4;
    float acc[16] = {};
    const float* mrow = mixd + i * JDIM;
    for (int j = 0; j < JDIM; j++) {
        float p = mrow[j];
        #pragma unroll
        for (int dd = 0; dd < 16; dd++)
            acc[dd] += p * vs[j * 64 + dbase + dd];
    }
    size_t o = ((size_t)(b * SROWS + n * 64 + i)) * DINNER + g * 64 + dbase;
    #pragma unroll
    for (int dd = 0; dd < 16; dd += 2)
        *reinterpret_cast<__half2*>(g_Oh + o + dd) = __floats2half2_rn(acc[dd], acc[dd + 1]);
}

// ---------------- zero out t=0 row ----------------
__global__ void zero_row0_kernel(float* __restrict__ out)
{
    int idx = blockIdx.x * blockDim.x + threadIdx.x;
    if (idx < BATCH * DMODEL) {
        int b = idx >> 10, d = idx & 1023;
        out[(size_t)b * 4097 * DMODEL + d] = 0.f;
    }
}

// ---------------- launch ----------------
extern "C" void kernel_launch(void* const* d_in, const int* in_sizes, int n_in,
                              void* d_out, int out_size)
{
    const float* seq   = (const float*)d_in[0];
    const float* ctx   = (const float*)d_in[1];
    const float* Wq    = (const float*)d_in[2];
    const float* Wkv   = (const float*)d_in[3];
    const float* Wout  = (const float*)d_in[4];
    const float* b_out = (const float*)d_in[5];
    const float* nullk = (const float*)d_in[6];
    const float* nullv = (const float*)d_in[7];
    const float* Wth   = (const float*)d_in[8];
    const float* bth   = (const float*)d_in[9];
    float* out = (float*)d_out;

    cudaFuncSetAttribute(mma_gemm_kernel, cudaFuncAttributeMaxDynamicSharedMemorySize, GEMM_SMEM);
    cudaFuncSetAttribute(attn_kernel,  cudaFuncAttributeMaxDynamicSharedMemorySize, 50176);
    cudaFuncSetAttribute(pvmix_kernel, cudaFuncAttributeMaxDynamicSharedMemorySize, 66048);

    __half *wq, *wkv, *wo, *sh, *ch_, *oh;
    float *q32, *kv32;
    cudaGetSymbolAddress((void**)&wq,  g_Wq);
    cudaGetSymbolAddress((void**)&wkv, g_Wkv);
    cudaGetSymbolAddress((void**)&wo,  g_Wo);
    cudaGetSymbolAddress((void**)&sh,  g_Sh);
    cudaGetSymbolAddress((void**)&ch_, g_Ch);
    cudaGetSymbolAddress((void**)&oh,  g_Oh);
    cudaGetSymbolAddress((void**)&q32,  g_Q);
    cudaGetSymbolAddress((void**)&kv32, g_KV);

    split_w_kernel<<<dim3(32, 32), dim3(32, 8)>>>(Wkv,  wkv, 1024, 1024);             // 1
    split_act_kernel<<<32768, 256>>>(ctx, ch_, 2);                                    // 2
    split_act_kernel<<<16384, 256>>>(seq, sh,  1);                                    // 3
    // KV = pad(context) @ Wkv                                                        // 4 (profiled)
    mma_gemm_kernel<<<dim3(8, 256), 256, GEMM_SMEM>>>(ch_, wkv, 1024u * 1024u, kv32,
                                                      32768, 1024, 1024, 1.0f, nullptr, 0);
    split_w_kernel<<<dim3(32, 16), dim3(32, 8)>>>(Wq, wq, 1024, 512);                 // 5
    // Q = (seq[:,1:] @ Wq) * 0.125                                                   // 6
    mma_gemm_kernel<<<dim3(4, 128), 256, GEMM_SMEM>>>(sh, wq, 512u * 1024u, q32,
                                                      16384, 512, 1024, 0.125f, nullptr, 0);
    attn_kernel<<<BATCH * NH * NCH, 256, 50176>>>(nullk);                             // 7
    pvmix_kernel<<<BATCH * NH * NCH, 256, 66048>>>(nullv, Wth, bth);                  // 8
    split_w_kernel<<<dim3(16, 32), dim3(32, 8)>>>(Wout, wo, 512, 1024);               // 9
    // out = O @ Wout + b_out, scattered to d_out rows t=1..4096                      // 10
    mma_gemm_kernel<<<dim3(8, 128), 256, GEMM_SMEM>>>(oh, wo, 1024u * 512u, out,
                                                      16384, 1024, 512, 1.0f, b_out, 2);
    zero_row0_kernel<<<4, 1024>>>(out);                                               // 11
}